// round 2
// baseline (speedup 1.0000x reference)
#include <cuda_runtime.h>
#include <math.h>
#include <stdint.h>

// Problem constants
#define B_ 8
#define S_ 512
#define C_ 512
#define H_ 8
#define D_ 64
#define E_ 6
#define M_ 4096          // B*S
#define RH_ 512
#define EPS_ 1e-8f

// d_out layout: aggregated (M*C), stacked (M*E*C), sparse (M*E)
#define AGG_ELEMS   (M_*C_)            // 2,097,152
#define STACK_ELEMS (M_*E_*C_)         // 12,582,912
#define STACK_OFF   (AGG_ELEMS)
#define SPARSE_OFF  (AGG_ELEMS + STACK_ELEMS)

// Scratch (device globals — no runtime allocation allowed)
__device__ float g_Q [E_*M_*C_];
__device__ float g_K [E_*M_*C_];
__device__ float g_V [E_*M_*C_];
__device__ float g_XO[E_*M_*C_];
__device__ float g_H [E_*M_*C_];
__device__ float g_RH[M_*RH_];

__device__ __forceinline__ float gelu_exact(float v) {
    return 0.5f * v * (1.0f + erff(v * 0.70710678118654752f));
}

// ---------------------------------------------------------------------------
// Generic batched SGEMM: out[z][m, n] = epi( sum_k A[z][m,k] * W[z][k,n] + bias[z][n] )
// K = N = 512 fixed. A row-major lda=512. W row-major ldb=512.
// mode 0: v = (acc+bias)*alpha
// mode 1: v = gelu(acc+bias)
// mode 2: v = acc + bias + res[z][m*512+n]
// ---------------------------------------------------------------------------
#define BM 128
#define BN 128
#define BK 16

__global__ __launch_bounds__(256) void gemm_kernel(
    const float* __restrict__ A,  long strideAe,
    const float* __restrict__ W,  long strideWe,
    const float* __restrict__ bias, long strideBe,
    float* __restrict__ out, long strideOe, int ldo,
    const float* __restrict__ res, long strideRe,
    float alpha, int mode)
{
    int z = blockIdx.z;
    A    += z * strideAe;
    W    += z * strideWe;
    bias += z * strideBe;
    out  += z * strideOe;
    const float* resz = res ? res + z * strideRe : nullptr;

    int m0 = blockIdx.y * BM;
    int n0 = blockIdx.x * BN;

    __shared__ float As[BK][BM + 4];   // [k][m], padded
    __shared__ float Bs[BK][BN + 4];   // [k][n], padded

    int tid = threadIdx.x;
    int tx = tid & 15;      // 0..15 -> n
    int ty = tid >> 4;      // 0..15 -> m

    float acc[8][8];
#pragma unroll
    for (int i = 0; i < 8; i++)
#pragma unroll
        for (int j = 0; j < 8; j++) acc[i][j] = 0.f;

    for (int k0 = 0; k0 < 512; k0 += BK) {
        // load A tile 128x16 (512 float4)
#pragma unroll
        for (int it = 0; it < 2; it++) {
            int lin = tid + it * 256;              // 0..511
            int r   = lin >> 2;                    // 0..127
            int kc  = (lin & 3) << 2;              // 0,4,8,12
            float4 v = *(const float4*)(A + (long)(m0 + r) * 512 + k0 + kc);
            As[kc + 0][r] = v.x;
            As[kc + 1][r] = v.y;
            As[kc + 2][r] = v.z;
            As[kc + 3][r] = v.w;
        }
        // load B tile 16x128 (512 float4)
#pragma unroll
        for (int it = 0; it < 2; it++) {
            int lin = tid + it * 256;
            int kr  = lin >> 5;                    // 0..15
            int nc  = (lin & 31) << 2;             // 0..124
            *(float4*)&Bs[kr][nc] =
                *(const float4*)(W + (long)(k0 + kr) * 512 + n0 + nc);
        }
        __syncthreads();

#pragma unroll
        for (int k = 0; k < BK; k++) {
            float a[8], b[8];
            *(float4*)&a[0] = *(float4*)&As[k][ty * 8];
            *(float4*)&a[4] = *(float4*)&As[k][ty * 8 + 4];
            *(float4*)&b[0] = *(float4*)&Bs[k][tx * 8];
            *(float4*)&b[4] = *(float4*)&Bs[k][tx * 8 + 4];
#pragma unroll
            for (int i = 0; i < 8; i++)
#pragma unroll
                for (int j = 0; j < 8; j++)
                    acc[i][j] += a[i] * b[j];
        }
        __syncthreads();
    }

    // epilogue
#pragma unroll
    for (int i = 0; i < 8; i++) {
        int m = m0 + ty * 8 + i;
#pragma unroll
        for (int j = 0; j < 8; j++) {
            int n = n0 + tx * 8 + j;
            float v = acc[i][j] + bias[n];
            if (mode == 0)      v *= alpha;
            else if (mode == 1) v = gelu_exact(v);
            else                v += resz[(long)m * 512 + n];
            out[(long)m * ldo + n] = v;
        }
    }
}

// ---------------------------------------------------------------------------
// Attention: per (e,b,h), flash-style over 64-query x 64-key tiles.
// Q already scaled. Layouts: Q/K/V/XO are (E,B,S,C), head h occupies cols h*64..h*64+63.
// mask is int32 {0,1}, shape (B, 3*S); we use the first S per batch row.
// ---------------------------------------------------------------------------
#define APAD 68   // row pitch (floats) for 64-wide tiles

__global__ __launch_bounds__(256) void attn_kernel(
    const float* __restrict__ Q, const float* __restrict__ K,
    const float* __restrict__ V, const int* __restrict__ mask,
    float* __restrict__ XO)
{
    extern __shared__ float sm[];
    float* QsT  = sm;                     // [d][i]  64x68
    float* KsT  = QsT + 64 * APAD;        // [d][j]  (reused as PsT[j][i])
    float* Vs   = KsT + 64 * APAD;        // [j][d]
    float* Ps   = Vs  + 64 * APAD;        // [i][j]
    float* rowm = Ps  + 64 * APAD;        // [64]
    float* rowl = rowm + 64;              // [64]
    float* rowsc= rowl + 64;              // [64]

    int tid = threadIdx.x;
    int h   = blockIdx.y;
    int eb  = blockIdx.z;                 // e*B + b
    int b   = eb & (B_ - 1);
    int q0  = blockIdx.x * 64;

    const float* Qp = Q + (long)eb * S_ * C_ + h * 64;
    const float* Kp = K + (long)eb * S_ * C_ + h * 64;
    const float* Vp = V + (long)eb * S_ * C_ + h * 64;
    float*       Op = XO + (long)eb * S_ * C_ + h * 64;
    const int* mrow = mask + b * 3 * S_;

    // load Q tile transposed: QsT[d][i]
#pragma unroll
    for (int it = 0; it < 4; it++) {
        int lin = tid + it * 256;          // 0..1023
        int r   = lin >> 4;                // query row 0..63
        int c4  = (lin & 15) << 2;         // d 0..60
        float4 v = *(const float4*)(Qp + (long)(q0 + r) * C_ + c4);
        QsT[(c4 + 0) * APAD + r] = v.x;
        QsT[(c4 + 1) * APAD + r] = v.y;
        QsT[(c4 + 2) * APAD + r] = v.z;
        QsT[(c4 + 3) * APAD + r] = v.w;
    }
    if (tid < 64) { rowm[tid] = -1e30f; rowl[tid] = 0.f; }

    int ci = (tid >> 4) << 2;   // 4 rows (i)
    int cj = (tid & 15) << 2;   // 4 cols (j for S stage, d for O stage)

    float oacc[4][4];
#pragma unroll
    for (int i = 0; i < 4; i++)
#pragma unroll
        for (int j = 0; j < 4; j++) oacc[i][j] = 0.f;

    for (int t0 = 0; t0 < S_; t0 += 64) {
        __syncthreads();   // protects Q init / previous-tile consumers
        // load K transposed + V
#pragma unroll
        for (int it = 0; it < 4; it++) {
            int lin = tid + it * 256;
            int r   = lin >> 4;
            int c4  = (lin & 15) << 2;
            float4 kv = *(const float4*)(Kp + (long)(t0 + r) * C_ + c4);
            KsT[(c4 + 0) * APAD + r] = kv.x;
            KsT[(c4 + 1) * APAD + r] = kv.y;
            KsT[(c4 + 2) * APAD + r] = kv.z;
            KsT[(c4 + 3) * APAD + r] = kv.w;
            float4 vv = *(const float4*)(Vp + (long)(t0 + r) * C_ + c4);
            *(float4*)&Vs[r * APAD + c4] = vv;
        }
        __syncthreads();

        // S = Q @ K^T (rank-1 over d)
        float sacc[4][4];
#pragma unroll
        for (int i = 0; i < 4; i++)
#pragma unroll
            for (int j = 0; j < 4; j++) sacc[i][j] = 0.f;
#pragma unroll 16
        for (int d = 0; d < 64; d++) {
            float4 a4 = *(float4*)&QsT[d * APAD + ci];
            float4 b4 = *(float4*)&KsT[d * APAD + cj];
            float a[4] = {a4.x, a4.y, a4.z, a4.w};
            float bb[4] = {b4.x, b4.y, b4.z, b4.w};
#pragma unroll
            for (int i = 0; i < 4; i++)
#pragma unroll
                for (int j = 0; j < 4; j++)
                    sacc[i][j] += a[i] * bb[j];
        }
        // write S tile with key mask
#pragma unroll
        for (int jj = 0; jj < 4; jj++) {
            bool ok = mrow[t0 + cj + jj] != 0;
#pragma unroll
            for (int ii = 0; ii < 4; ii++) {
                float s = ok ? sacc[ii][jj] : -1e30f;
                Ps[(ci + ii) * APAD + cj + jj] = s;
            }
        }
        __syncthreads();

        // online softmax: one quad of threads per row
        {
            int row  = tid >> 2;
            int quad = tid & 3;
            float p[16];
            const float* prow = &Ps[row * APAD + quad * 16];
            float mx = -1e30f;
#pragma unroll
            for (int t4 = 0; t4 < 4; t4++) {
                float4 v = *(const float4*)(prow + t4 * 4);
                p[t4*4+0] = v.x; p[t4*4+1] = v.y; p[t4*4+2] = v.z; p[t4*4+3] = v.w;
                mx = fmaxf(mx, fmaxf(fmaxf(v.x, v.y), fmaxf(v.z, v.w)));
            }
            mx = fmaxf(mx, __shfl_xor_sync(0xffffffffu, mx, 1));
            mx = fmaxf(mx, __shfl_xor_sync(0xffffffffu, mx, 2));
            float oldm = rowm[row];
            float newm = fmaxf(oldm, mx);
            float sum = 0.f;
#pragma unroll
            for (int t = 0; t < 16; t++) {
                float e = __expf(p[t] - newm);
                p[t] = e;
                sum += e;
            }
            sum += __shfl_xor_sync(0xffffffffu, sum, 1);
            sum += __shfl_xor_sync(0xffffffffu, sum, 2);
            float scale = __expf(oldm - newm);
            // write P transposed into KsT buffer: PsT[j][i]
#pragma unroll
            for (int t = 0; t < 16; t++)
                KsT[(quad * 16 + t) * APAD + row] = p[t];
            __syncwarp();
            if (quad == 0) {
                rowl[row] = rowl[row] * scale + sum;
                rowm[row] = newm;
                rowsc[row] = scale;
            }
        }
        __syncthreads();

        // rescale O, then O += P @ V (rank-1 over j); PsT lives in KsT
#pragma unroll
        for (int ii = 0; ii < 4; ii++) {
            float sc = rowsc[ci + ii];
#pragma unroll
            for (int jj = 0; jj < 4; jj++) oacc[ii][jj] *= sc;
        }
#pragma unroll 16
        for (int j = 0; j < 64; j++) {
            float4 a4 = *(float4*)&KsT[j * APAD + ci];   // PsT[j][i]
            float4 b4 = *(float4*)&Vs[j * APAD + cj];    // V[j][d]
            float a[4] = {a4.x, a4.y, a4.z, a4.w};
            float bb[4] = {b4.x, b4.y, b4.z, b4.w};
#pragma unroll
            for (int i = 0; i < 4; i++)
#pragma unroll
                for (int jj = 0; jj < 4; jj++)
                    oacc[i][jj] += a[i] * bb[jj];
        }
    }

    // final normalize + write
#pragma unroll
    for (int ii = 0; ii < 4; ii++) {
        float l = rowl[ci + ii];
        float inv = (l > 0.f) ? (1.f / l) : 0.f;
        float4 o;
        o.x = oacc[ii][0] * inv;
        o.y = oacc[ii][1] * inv;
        o.z = oacc[ii][2] * inv;
        o.w = oacc[ii][3] * inv;
        *(float4*)(Op + (long)(q0 + ci + ii) * C_ + cj) = o;
    }
}

// ---------------------------------------------------------------------------
// Router: logits = rh @ rw2 + rb2, softmax, top-2 (strict >, matches lax.top_k
// tie order), renormalize. One warp per token.
// ---------------------------------------------------------------------------
__global__ __launch_bounds__(256) void router_kernel(
    const float* __restrict__ rh, const float* __restrict__ rw2,
    const float* __restrict__ rb2, float* __restrict__ sparse)
{
    int gwarp = (blockIdx.x * blockDim.x + threadIdx.x) >> 5;
    int lane  = threadIdx.x & 31;
    if (gwarp >= M_) return;

    const float* r = rh + (long)gwarp * RH_;
    float acc[E_];
#pragma unroll
    for (int e = 0; e < E_; e++) acc[e] = 0.f;
    for (int hh = lane; hh < RH_; hh += 32) {
        float xv = r[hh];
        const float* w = rw2 + hh * E_;
#pragma unroll
        for (int e = 0; e < E_; e++) acc[e] += xv * w[e];
    }
#pragma unroll
    for (int off = 16; off > 0; off >>= 1)
#pragma unroll
        for (int e = 0; e < E_; e++)
            acc[e] += __shfl_xor_sync(0xffffffffu, acc[e], off);

    if (lane == 0) {
        float lg[E_];
        float mx = -1e30f;
#pragma unroll
        for (int e = 0; e < E_; e++) { lg[e] = acc[e] + rb2[e]; mx = fmaxf(mx, lg[e]); }
        float sum = 0.f;
#pragma unroll
        for (int e = 0; e < E_; e++) { lg[e] = __expf(lg[e] - mx); sum += lg[e]; }
        float inv = 1.f / sum;
#pragma unroll
        for (int e = 0; e < E_; e++) lg[e] *= inv;     // probs
        // top-2 (first max, then second max; strict > keeps lowest index on tie)
        int i1 = 0;
#pragma unroll
        for (int e = 1; e < E_; e++) if (lg[e] > lg[i1]) i1 = e;
        int i2 = (i1 == 0) ? 1 : 0;
#pragma unroll
        for (int e = 0; e < E_; e++) if (e != i1 && lg[e] > lg[i2]) i2 = e;
        float denom = fmaxf(lg[i1] + lg[i2], EPS_);
        float out[E_];
#pragma unroll
        for (int e = 0; e < E_; e++) out[e] = 0.f;
        out[i1] = lg[i1] / denom;
        out[i2] = lg[i2] / denom;
        float* o = sparse + (long)gwarp * E_;
#pragma unroll
        for (int e = 0; e < E_; e++) o[e] = out[e];
    }
}

// ---------------------------------------------------------------------------
// Aggregation: agg[m, c] = sum_e sparse[m,e] * stacked[m,e,c]
// ---------------------------------------------------------------------------
__global__ __launch_bounds__(256) void agg_kernel(
    const float* __restrict__ stacked, const float* __restrict__ sparse,
    float* __restrict__ agg)
{
    int idx = blockIdx.x * blockDim.x + threadIdx.x;   // (m, c/4)
    if (idx >= M_ * (C_ / 4)) return;
    int m  = idx >> 7;
    int c  = (idx & 127) << 2;
    const float* sp = sparse + (long)m * E_;
    float w[E_];
#pragma unroll
    for (int e = 0; e < E_; e++) w[e] = sp[e];
    float4 a = {0.f, 0.f, 0.f, 0.f};
#pragma unroll
    for (int e = 0; e < E_; e++) {
        float4 v = *(const float4*)(stacked + ((long)m * E_ + e) * C_ + c);
        a.x += w[e] * v.x; a.y += w[e] * v.y; a.z += w[e] * v.z; a.w += w[e] * v.w;
    }
    *(float4*)(agg + (long)m * C_ + c) = a;
}

// ---------------------------------------------------------------------------
// Launch
// ---------------------------------------------------------------------------
extern "C" void kernel_launch(void* const* d_in, const int* in_sizes, int n_in,
                              void* d_out, int out_size)
{
    const float* x    = (const float*)d_in[0];
    const int*   mask = (const int*)d_in[1];     // bool -> int32 on device
    const float* qw   = (const float*)d_in[2];
    const float* qb   = (const float*)d_in[3];
    const float* kw   = (const float*)d_in[4];
    const float* kb   = (const float*)d_in[5];
    const float* vw   = (const float*)d_in[6];
    const float* vb   = (const float*)d_in[7];
    const float* fc1w = (const float*)d_in[8];
    const float* fc1b = (const float*)d_in[9];
    const float* fc2w = (const float*)d_in[10];
    const float* fc2b = (const float*)d_in[11];
    const float* rw1  = (const float*)d_in[12];
    const float* rb1  = (const float*)d_in[13];
    const float* rw2  = (const float*)d_in[14];
    const float* rb2  = (const float*)d_in[15];

    float* out     = (float*)d_out;
    float* agg     = out;
    float* stacked = out + STACK_OFF;
    float* sparse  = out + SPARSE_OFF;

    float *gq, *gk, *gv, *gxo, *gh, *grh;
    cudaGetSymbolAddress((void**)&gq,  g_Q);
    cudaGetSymbolAddress((void**)&gk,  g_K);
    cudaGetSymbolAddress((void**)&gv,  g_V);
    cudaGetSymbolAddress((void**)&gxo, g_XO);
    cudaGetSymbolAddress((void**)&gh,  g_H);
    cudaGetSymbolAddress((void**)&grh, g_RH);

    const long WE = (long)C_ * C_;     // per-expert weight stride
    const long OE = (long)M_ * C_;     // per-expert activation stride

    dim3 gg(C_ / BN, M_ / BM, E_);     // (4, 32, 6)
    dim3 gr(C_ / BN, M_ / BM, 1);

    // Q = (x@qw + qb) * D^-0.5 ; K, V plain
    gemm_kernel<<<gg, 256>>>(x, 0, qw, WE, qb, C_, gq, OE, C_, nullptr, 0, 0.125f, 0);
    gemm_kernel<<<gg, 256>>>(x, 0, kw, WE, kb, C_, gk, OE, C_, nullptr, 0, 1.0f, 0);
    gemm_kernel<<<gg, 256>>>(x, 0, vw, WE, vb, C_, gv, OE, C_, nullptr, 0, 1.0f, 0);

    // attention
    {
        static_assert(4 * 64 * APAD * 4 + 3 * 64 * 4 <= 80 * 1024, "smem");
        int smem = 4 * 64 * APAD * sizeof(float) + 3 * 64 * sizeof(float);
        cudaFuncSetAttribute(attn_kernel, cudaFuncAttributeMaxDynamicSharedMemorySize, smem);
        dim3 ag(S_ / 64, H_, E_ * B_); // (8, 8, 48)
        attn_kernel<<<ag, 256, smem>>>(gq, gk, gv, mask, gxo);
    }

    // FFN: h = gelu(xo@fc1w + fc1b); stacked[b,s,e,:] = xo + h@fc2w + fc2b
    gemm_kernel<<<gg, 256>>>(gxo, OE, fc1w, WE, fc1b, C_, gh, OE, C_, nullptr, 0, 1.0f, 1);
    gemm_kernel<<<gg, 256>>>(gh, OE, fc2w, WE, fc2b, C_, stacked, C_, E_ * C_, gxo, OE, 1.0f, 2);

    // Router: rh = gelu(x@rw1 + rb1); then logits/softmax/top2
    gemm_kernel<<<gr, 256>>>(x, 0, rw1, 0, rb1, 0, grh, 0, RH_, nullptr, 0, 1.0f, 1);
    router_kernel<<<(M_ * 32 + 255) / 256, 256>>>(grh, rw2, rb2, sparse);

    // Aggregate
    agg_kernel<<<(M_ * (C_ / 4) + 255) / 256, 256>>>(stacked, sparse, agg);
}

// round 7
// speedup vs baseline: 1.5731x; 1.5731x over previous
#include <cuda_runtime.h>
#include <cuda_bf16.h>
#include <math.h>
#include <stdint.h>

// Problem constants
#define B_ 8
#define S_ 512
#define C_ 512
#define H_ 8
#define D_ 64
#define E_ 6
#define M_ 4096          // B*S
#define RH_ 512
#define EPS_ 1e-8f

// d_out layout: aggregated (M*C), stacked (M*E*C), sparse (M*E)
#define AGG_ELEMS   (M_*C_)
#define STACK_ELEMS (M_*E_*C_)
#define STACK_OFF   (AGG_ELEMS)
#define SPARSE_OFF  (AGG_ELEMS + STACK_ELEMS)

// Scratch (device globals — no runtime allocation allowed)
__device__ float g_Q [E_*M_*C_];
__device__ float g_K [E_*M_*C_];
__device__ float g_V [E_*M_*C_];
__device__ float g_XO[E_*M_*C_];
__device__ float g_H [E_*M_*C_];
__device__ float g_RH[M_*RH_];

__device__ __forceinline__ float gelu_exact(float v) {
    return 0.5f * v * (1.0f + erff(v * 0.70710678118654752f));
}

__device__ __forceinline__ void bf16_split(float f, unsigned short& h, unsigned short& l) {
    __nv_bfloat16 bh = __float2bfloat16_rn(f);
    float r = f - __bfloat162float(bh);
    __nv_bfloat16 bl = __float2bfloat16_rn(r);
    h = __bfloat16_as_ushort(bh);
    l = __bfloat16_as_ushort(bl);
}

__device__ __forceinline__ uint32_t pack2(unsigned short lo16, unsigned short hi16) {
    return ((uint32_t)hi16 << 16) | (uint32_t)lo16;
}

__device__ __forceinline__ void mma_bf16(float4& d,
    uint32_t a0, uint32_t a1, uint32_t a2, uint32_t a3,
    uint32_t b0, uint32_t b1)
{
    asm volatile(
        "mma.sync.aligned.m16n8k16.row.col.f32.bf16.bf16.f32 "
        "{%0,%1,%2,%3}, {%4,%5,%6,%7}, {%8,%9}, {%0,%1,%2,%3};\n"
        : "+f"(d.x), "+f"(d.y), "+f"(d.z), "+f"(d.w)
        : "r"(a0), "r"(a1), "r"(a2), "r"(a3), "r"(b0), "r"(b1));
}

// ---------------------------------------------------------------------------
// Batched bf16x3 (split) tensor-core GEMM, fp32-class accuracy.
// out[z][m,n] = epi(sum_k A[z][m,k]*W[z][k,n] + bias[z][n])
// K = N = 512. Tile 128x128x32. 256 threads = 8 warps of 32x64.
// mode 0: (acc+bias)*alpha ; mode 1: gelu(acc+bias) ; mode 2: acc+bias+res
// ---------------------------------------------------------------------------
#define BM 128
#define BN 128
#define BK 32
#define KP 16        // kpairs per tile
#define APITCH 20    // A row pitch in words (16 kpairs + 4 pad): banks (20g+t) distinct
#define BPITCH 136   // B kpair-row pitch in words (128 n + 8 pad): banks (8t+g) distinct
#define AWORDS (BM*APITCH)   // 2560
#define BWORDS (KP*BPITCH)   // 2176
#define GSMEM  ((2*AWORDS + 2*BWORDS) * 2 * 4)  // hi+lo, double buffer, bytes = 75776

__global__ __launch_bounds__(256) void gemm_bf16x3_kernel(
    const float* __restrict__ A,  long strideAe,
    const float* __restrict__ W,  long strideWe,
    const float* __restrict__ bias, long strideBe,
    float* __restrict__ out, long strideOe, int ldo,
    const float* __restrict__ res, long strideRe,
    float alpha, int mode)
{
    int z = blockIdx.z;
    A    += z * strideAe;
    W    += z * strideWe;
    bias += z * strideBe;
    out  += z * strideOe;
    const float* resz = res ? res + z * strideRe : nullptr;

    int m0 = blockIdx.y * BM;
    int n0 = blockIdx.x * BN;

    extern __shared__ uint32_t smw[];
    uint32_t* Ahi = smw;                      // [2][AWORDS]
    uint32_t* Alo = Ahi + 2 * AWORDS;
    uint32_t* Bhi = Alo + 2 * AWORDS;         // [2][BWORDS]
    uint32_t* Blo = Bhi + 2 * BWORDS;

    int tid  = threadIdx.x;
    int lane = tid & 31;
    int warp = tid >> 5;
    int wm   = warp & 3;    // rows wm*32
    int wn   = warp >> 2;   // cols wn*64
    int g    = lane >> 2;   // group 0..7
    int t    = lane & 3;    // thread-in-group

    // A gmem: 4 float4 per thread per tile
    int ar = tid >> 3;            // 0..31
    int ac = (tid & 7) << 2;      // k offset 0,4,...,28
    const float* aptr = A + (long)(m0 + ar) * 512 + ac;
    int abase = ar * APITCH + (ac >> 1);

    // B gmem: 16 scalars per thread per tile; warp w owns kpairs {2w, 2w+1}
    const float* bptr = W + n0 + lane;    // + (kt*BK + 4*warp + 2*p + s)*512 + 32*j

    float4 acc[2][8];
#pragma unroll
    for (int i = 0; i < 2; i++)
#pragma unroll
        for (int j = 0; j < 8; j++) acc[i][j] = make_float4(0.f, 0.f, 0.f, 0.f);

    // ---- tile load helper (macro-ish lambdas) ----
    auto store_tile = [&](int buf, const float4 av[4], const float bv[2][4][2]) {
        uint32_t* ah = Ahi + buf * AWORDS;
        uint32_t* al = Alo + buf * AWORDS;
#pragma unroll
        for (int i = 0; i < 4; i++) {
            unsigned short hx, lx, hy, ly, hz, lz, hw, lw;
            bf16_split(av[i].x, hx, lx);
            bf16_split(av[i].y, hy, ly);
            bf16_split(av[i].z, hz, lz);
            bf16_split(av[i].w, hw, lw);
            int a0 = abase + 32 * i * APITCH;
            ah[a0]     = pack2(hx, hy);
            ah[a0 + 1] = pack2(hz, hw);
            al[a0]     = pack2(lx, ly);
            al[a0 + 1] = pack2(lz, lw);
        }
        uint32_t* bh = Bhi + buf * BWORDS;
        uint32_t* bl = Blo + buf * BWORDS;
#pragma unroll
        for (int p = 0; p < 2; p++) {
            int kp = 2 * warp + p;
#pragma unroll
            for (int j = 0; j < 4; j++) {
                unsigned short h0, l0, h1, l1;
                bf16_split(bv[p][j][0], h0, l0);
                bf16_split(bv[p][j][1], h1, l1);
                int off = kp * BPITCH + lane + 32 * j;
                bh[off] = pack2(h0, h1);
                bl[off] = pack2(l0, l1);
            }
        }
    };

    // preload tile 0
    {
        float4 av[4];
        float  bv[2][4][2];
#pragma unroll
        for (int i = 0; i < 4; i++)
            av[i] = *(const float4*)(aptr + (long)(32 * i) * 512);
#pragma unroll
        for (int p = 0; p < 2; p++)
#pragma unroll
            for (int j = 0; j < 4; j++)
#pragma unroll
                for (int s = 0; s < 2; s++)
                    bv[p][j][s] = bptr[(long)(4 * warp + 2 * p + s) * 512 + 32 * j];
        store_tile(0, av, bv);
    }
    __syncthreads();

    const int NT = 512 / BK;  // 16
    float4 pav[4];
    float  pbv[2][4][2];

    for (int kt = 0; kt < NT; kt++) {
        int cur = kt & 1;
        if (kt + 1 < NT) {
            const float* ap = aptr + (kt + 1) * BK;
#pragma unroll
            for (int i = 0; i < 4; i++)
                pav[i] = *(const float4*)(ap + (long)(32 * i) * 512);
#pragma unroll
            for (int p = 0; p < 2; p++)
#pragma unroll
                for (int j = 0; j < 4; j++)
#pragma unroll
                    for (int s = 0; s < 2; s++)
                        pbv[p][j][s] = bptr[(long)((kt + 1) * BK + 4 * warp + 2 * p + s) * 512 + 32 * j];
        }

        const uint32_t* ah = Ahi + cur * AWORDS;
        const uint32_t* al = Alo + cur * AWORDS;
        const uint32_t* bh = Bhi + cur * BWORDS;
        const uint32_t* bl = Blo + cur * BWORDS;

#pragma unroll
        for (int kk = 0; kk < 2; kk++) {
            uint32_t afh[2][4], afl[2][4];
#pragma unroll
            for (int mt = 0; mt < 2; mt++) {
                int row = wm * 32 + mt * 16 + g;
                int base = row * APITCH + kk * 8 + t;
                afh[mt][0] = ah[base];
                afh[mt][1] = ah[base + 8 * APITCH];
                afh[mt][2] = ah[base + 4];
                afh[mt][3] = ah[base + 8 * APITCH + 4];
                afl[mt][0] = al[base];
                afl[mt][1] = al[base + 8 * APITCH];
                afl[mt][2] = al[base + 4];
                afl[mt][3] = al[base + 8 * APITCH + 4];
            }
#pragma unroll
            for (int nt = 0; nt < 8; nt++) {
                int col = wn * 64 + nt * 8 + g;
                int bbase = (kk * 8 + t) * BPITCH + col;
                uint32_t bh0 = bh[bbase];
                uint32_t bh1 = bh[bbase + 4 * BPITCH];
                uint32_t bl0 = bl[bbase];
                uint32_t bl1 = bl[bbase + 4 * BPITCH];
#pragma unroll
                for (int mt = 0; mt < 2; mt++) {
                    mma_bf16(acc[mt][nt], afh[mt][0], afh[mt][1], afh[mt][2], afh[mt][3], bh0, bh1);
                    mma_bf16(acc[mt][nt], afh[mt][0], afh[mt][1], afh[mt][2], afh[mt][3], bl0, bl1);
                    mma_bf16(acc[mt][nt], afl[mt][0], afl[mt][1], afl[mt][2], afl[mt][3], bh0, bh1);
                }
            }
        }

        if (kt + 1 < NT) {
            store_tile(cur ^ 1, pav, pbv);
            __syncthreads();
        }
    }

    // epilogue: c layout rows (g, g+8), cols (2t, 2t+1)
#pragma unroll
    for (int mt = 0; mt < 2; mt++) {
        int R0 = m0 + wm * 32 + mt * 16 + g;
        int R1 = R0 + 8;
#pragma unroll
        for (int nt = 0; nt < 8; nt++) {
            int N0 = n0 + wn * 64 + nt * 8 + 2 * t;
            float b0 = bias[N0], b1 = bias[N0 + 1];
            float4 a = acc[mt][nt];
            float v0 = a.x + b0, v1 = a.y + b1, v2 = a.z + b0, v3 = a.w + b1;
            if (mode == 0)      { v0 *= alpha; v1 *= alpha; v2 *= alpha; v3 *= alpha; }
            else if (mode == 1) { v0 = gelu_exact(v0); v1 = gelu_exact(v1); v2 = gelu_exact(v2); v3 = gelu_exact(v3); }
            else {
                float2 r0 = *(const float2*)(resz + (long)R0 * 512 + N0);
                float2 r1 = *(const float2*)(resz + (long)R1 * 512 + N0);
                v0 += r0.x; v1 += r0.y; v2 += r1.x; v3 += r1.y;
            }
            *(float2*)(out + (long)R0 * ldo + N0) = make_float2(v0, v1);
            *(float2*)(out + (long)R1 * ldo + N0) = make_float2(v2, v3);
        }
    }
}

// ---------------------------------------------------------------------------
// Exact fp32 SIMT GEMM (router path only — selection must match fp32 exactly-ish)
// ---------------------------------------------------------------------------
#define FBM 128
#define FBN 128
#define FBK 16

__global__ __launch_bounds__(256) void gemm_f32_kernel(
    const float* __restrict__ A,
    const float* __restrict__ W,
    const float* __restrict__ bias,
    float* __restrict__ out)
{
    int m0 = blockIdx.y * FBM;
    int n0 = blockIdx.x * FBN;

    __shared__ float As[FBK][FBM + 4];
    __shared__ float Bs[FBK][FBN + 4];

    int tid = threadIdx.x;
    int tx = tid & 15;
    int ty = tid >> 4;

    float acc[8][8];
#pragma unroll
    for (int i = 0; i < 8; i++)
#pragma unroll
        for (int j = 0; j < 8; j++) acc[i][j] = 0.f;

    for (int k0 = 0; k0 < 512; k0 += FBK) {
#pragma unroll
        for (int it = 0; it < 2; it++) {
            int lin = tid + it * 256;
            int r   = lin >> 2;
            int kc  = (lin & 3) << 2;
            float4 v = *(const float4*)(A + (long)(m0 + r) * 512 + k0 + kc);
            As[kc + 0][r] = v.x;
            As[kc + 1][r] = v.y;
            As[kc + 2][r] = v.z;
            As[kc + 3][r] = v.w;
        }
#pragma unroll
        for (int it = 0; it < 2; it++) {
            int lin = tid + it * 256;
            int kr  = lin >> 5;
            int nc  = (lin & 31) << 2;
            *(float4*)&Bs[kr][nc] =
                *(const float4*)(W + (long)(k0 + kr) * 512 + n0 + nc);
        }
        __syncthreads();

#pragma unroll
        for (int k = 0; k < FBK; k++) {
            float a[8], b[8];
            *(float4*)&a[0] = *(float4*)&As[k][ty * 8];
            *(float4*)&a[4] = *(float4*)&As[k][ty * 8 + 4];
            *(float4*)&b[0] = *(float4*)&Bs[k][tx * 8];
            *(float4*)&b[4] = *(float4*)&Bs[k][tx * 8 + 4];
#pragma unroll
            for (int i = 0; i < 8; i++)
#pragma unroll
                for (int j = 0; j < 8; j++)
                    acc[i][j] += a[i] * b[j];
        }
        __syncthreads();
    }

#pragma unroll
    for (int i = 0; i < 8; i++) {
        int m = m0 + ty * 8 + i;
#pragma unroll
        for (int j = 0; j < 8; j++) {
            int n = n0 + tx * 8 + j;
            out[(long)m * 512 + n] = gelu_exact(acc[i][j] + bias[n]);
        }
    }
}

// ---------------------------------------------------------------------------
// Attention: per (e,b,h), flash-style over 64-query x 64-key tiles. fp32.
// ---------------------------------------------------------------------------
#define APAD 68

__global__ __launch_bounds__(256) void attn_kernel(
    const float* __restrict__ Q, const float* __restrict__ K,
    const float* __restrict__ V, const int* __restrict__ mask,
    float* __restrict__ XO)
{
    extern __shared__ float sm[];
    float* QsT  = sm;
    float* KsT  = QsT + 64 * APAD;
    float* Vs   = KsT + 64 * APAD;
    float* Ps   = Vs  + 64 * APAD;
    float* rowm = Ps  + 64 * APAD;
    float* rowl = rowm + 64;
    float* rowsc= rowl + 64;

    int tid = threadIdx.x;
    int h   = blockIdx.y;
    int eb  = blockIdx.z;
    int b   = eb & (B_ - 1);
    int q0  = blockIdx.x * 64;

    const float* Qp = Q + (long)eb * S_ * C_ + h * 64;
    const float* Kp = K + (long)eb * S_ * C_ + h * 64;
    const float* Vp = V + (long)eb * S_ * C_ + h * 64;
    float*       Op = XO + (long)eb * S_ * C_ + h * 64;
    const int* mrow = mask + b * 3 * S_;

#pragma unroll
    for (int it = 0; it < 4; it++) {
        int lin = tid + it * 256;
        int r   = lin >> 4;
        int c4  = (lin & 15) << 2;
        float4 v = *(const float4*)(Qp + (long)(q0 + r) * C_ + c4);
        QsT[(c4 + 0) * APAD + r] = v.x;
        QsT[(c4 + 1) * APAD + r] = v.y;
        QsT[(c4 + 2) * APAD + r] = v.z;
        QsT[(c4 + 3) * APAD + r] = v.w;
    }
    if (tid < 64) { rowm[tid] = -1e30f; rowl[tid] = 0.f; }

    int ci = (tid >> 4) << 2;
    int cj = (tid & 15) << 2;

    float oacc[4][4];
#pragma unroll
    for (int i = 0; i < 4; i++)
#pragma unroll
        for (int j = 0; j < 4; j++) oacc[i][j] = 0.f;

    for (int t0 = 0; t0 < S_; t0 += 64) {
        __syncthreads();
#pragma unroll
        for (int it = 0; it < 4; it++) {
            int lin = tid + it * 256;
            int r   = lin >> 4;
            int c4  = (lin & 15) << 2;
            float4 kv = *(const float4*)(Kp + (long)(t0 + r) * C_ + c4);
            KsT[(c4 + 0) * APAD + r] = kv.x;
            KsT[(c4 + 1) * APAD + r] = kv.y;
            KsT[(c4 + 2) * APAD + r] = kv.z;
            KsT[(c4 + 3) * APAD + r] = kv.w;
            float4 vv = *(const float4*)(Vp + (long)(t0 + r) * C_ + c4);
            *(float4*)&Vs[r * APAD + c4] = vv;
        }
        __syncthreads();

        float sacc[4][4];
#pragma unroll
        for (int i = 0; i < 4; i++)
#pragma unroll
            for (int j = 0; j < 4; j++) sacc[i][j] = 0.f;
#pragma unroll 16
        for (int d = 0; d < 64; d++) {
            float4 a4 = *(float4*)&QsT[d * APAD + ci];
            float4 b4 = *(float4*)&KsT[d * APAD + cj];
            float a[4] = {a4.x, a4.y, a4.z, a4.w};
            float bb[4] = {b4.x, b4.y, b4.z, b4.w};
#pragma unroll
            for (int i = 0; i < 4; i++)
#pragma unroll
                for (int j = 0; j < 4; j++)
                    sacc[i][j] += a[i] * bb[j];
        }
#pragma unroll
        for (int jj = 0; jj < 4; jj++) {
            bool ok = mrow[t0 + cj + jj] != 0;
#pragma unroll
            for (int ii = 0; ii < 4; ii++) {
                float s = ok ? sacc[ii][jj] : -1e30f;
                Ps[(ci + ii) * APAD + cj + jj] = s;
            }
        }
        __syncthreads();

        {
            int row  = tid >> 2;
            int quad = tid & 3;
            float p[16];
            const float* prow = &Ps[row * APAD + quad * 16];
            float mx = -1e30f;
#pragma unroll
            for (int t4 = 0; t4 < 4; t4++) {
                float4 v = *(const float4*)(prow + t4 * 4);
                p[t4*4+0] = v.x; p[t4*4+1] = v.y; p[t4*4+2] = v.z; p[t4*4+3] = v.w;
                mx = fmaxf(mx, fmaxf(fmaxf(v.x, v.y), fmaxf(v.z, v.w)));
            }
            mx = fmaxf(mx, __shfl_xor_sync(0xffffffffu, mx, 1));
            mx = fmaxf(mx, __shfl_xor_sync(0xffffffffu, mx, 2));
            float oldm = rowm[row];
            float newm = fmaxf(oldm, mx);
            float sum = 0.f;
#pragma unroll
            for (int tt = 0; tt < 16; tt++) {
                float e = __expf(p[tt] - newm);
                p[tt] = e;
                sum += e;
            }
            sum += __shfl_xor_sync(0xffffffffu, sum, 1);
            sum += __shfl_xor_sync(0xffffffffu, sum, 2);
            float scale = __expf(oldm - newm);
#pragma unroll
            for (int tt = 0; tt < 16; tt++)
                KsT[(quad * 16 + tt) * APAD + row] = p[tt];
            __syncwarp();
            if (quad == 0) {
                rowl[row] = rowl[row] * scale + sum;
                rowm[row] = newm;
                rowsc[row] = scale;
            }
        }
        __syncthreads();

#pragma unroll
        for (int ii = 0; ii < 4; ii++) {
            float sc = rowsc[ci + ii];
#pragma unroll
            for (int jj = 0; jj < 4; jj++) oacc[ii][jj] *= sc;
        }
#pragma unroll 16
        for (int j = 0; j < 64; j++) {
            float4 a4 = *(float4*)&KsT[j * APAD + ci];
            float4 b4 = *(float4*)&Vs[j * APAD + cj];
            float a[4] = {a4.x, a4.y, a4.z, a4.w};
            float bb[4] = {b4.x, b4.y, b4.z, b4.w};
#pragma unroll
            for (int i = 0; i < 4; i++)
#pragma unroll
                for (int jj = 0; jj < 4; jj++)
                    oacc[i][jj] += a[i] * bb[jj];
        }
    }

#pragma unroll
    for (int ii = 0; ii < 4; ii++) {
        float l = rowl[ci + ii];
        float inv = (l > 0.f) ? (1.f / l) : 0.f;
        float4 o;
        o.x = oacc[ii][0] * inv;
        o.y = oacc[ii][1] * inv;
        o.z = oacc[ii][2] * inv;
        o.w = oacc[ii][3] * inv;
        *(float4*)(Op + (long)(q0 + ci + ii) * C_ + cj) = o;
    }
}

// ---------------------------------------------------------------------------
// Router: logits + softmax + top-2 (strict >), renormalize. One warp/token.
// ---------------------------------------------------------------------------
__global__ __launch_bounds__(256) void router_kernel(
    const float* __restrict__ rh, const float* __restrict__ rw2,
    const float* __restrict__ rb2, float* __restrict__ sparse)
{
    int gwarp = (blockIdx.x * blockDim.x + threadIdx.x) >> 5;
    int lane  = threadIdx.x & 31;
    if (gwarp >= M_) return;

    const float* r = rh + (long)gwarp * RH_;
    float acc[E_];
#pragma unroll
    for (int e = 0; e < E_; e++) acc[e] = 0.f;
    for (int hh = lane; hh < RH_; hh += 32) {
        float xv = r[hh];
        const float* w = rw2 + hh * E_;
#pragma unroll
        for (int e = 0; e < E_; e++) acc[e] += xv * w[e];
    }
#pragma unroll
    for (int off = 16; off > 0; off >>= 1)
#pragma unroll
        for (int e = 0; e < E_; e++)
            acc[e] += __shfl_xor_sync(0xffffffffu, acc[e], off);

    if (lane == 0) {
        float lg[E_];
        float mx = -1e30f;
#pragma unroll
        for (int e = 0; e < E_; e++) { lg[e] = acc[e] + rb2[e]; mx = fmaxf(mx, lg[e]); }
        float sum = 0.f;
#pragma unroll
        for (int e = 0; e < E_; e++) { lg[e] = __expf(lg[e] - mx); sum += lg[e]; }
        float inv = 1.f / sum;
#pragma unroll
        for (int e = 0; e < E_; e++) lg[e] *= inv;
        int i1 = 0;
#pragma unroll
        for (int e = 1; e < E_; e++) if (lg[e] > lg[i1]) i1 = e;
        int i2 = (i1 == 0) ? 1 : 0;
#pragma unroll
        for (int e = 0; e < E_; e++) if (e != i1 && lg[e] > lg[i2]) i2 = e;
        float denom = fmaxf(lg[i1] + lg[i2], EPS_);
        float outv[E_];
#pragma unroll
        for (int e = 0; e < E_; e++) outv[e] = 0.f;
        outv[i1] = lg[i1] / denom;
        outv[i2] = lg[i2] / denom;
        float* o = sparse + (long)gwarp * E_;
#pragma unroll
        for (int e = 0; e < E_; e++) o[e] = outv[e];
    }
}

// ---------------------------------------------------------------------------
// Aggregation: agg[m,c] = sum_e sparse[m,e] * stacked[m,e,c]
// ---------------------------------------------------------------------------
__global__ __launch_bounds__(256) void agg_kernel(
    const float* __restrict__ stacked, const float* __restrict__ sparse,
    float* __restrict__ agg)
{
    int idx = blockIdx.x * blockDim.x + threadIdx.x;
    if (idx >= M_ * (C_ / 4)) return;
    int m  = idx >> 7;
    int c  = (idx & 127) << 2;
    const float* sp = sparse + (long)m * E_;
    float w[E_];
#pragma unroll
    for (int e = 0; e < E_; e++) w[e] = sp[e];
    float4 a = {0.f, 0.f, 0.f, 0.f};
#pragma unroll
    for (int e = 0; e < E_; e++) {
        float4 v = *(const float4*)(stacked + ((long)m * E_ + e) * C_ + c);
        a.x += w[e] * v.x; a.y += w[e] * v.y; a.z += w[e] * v.z; a.w += w[e] * v.w;
    }
    *(float4*)(agg + (long)m * C_ + c) = a;
}

// ---------------------------------------------------------------------------
// Launch
// ---------------------------------------------------------------------------
extern "C" void kernel_launch(void* const* d_in, const int* in_sizes, int n_in,
                              void* d_out, int out_size)
{
    const float* x    = (const float*)d_in[0];
    const int*   mask = (const int*)d_in[1];
    const float* qw   = (const float*)d_in[2];
    const float* qb   = (const float*)d_in[3];
    const float* kw   = (const float*)d_in[4];
    const float* kb   = (const float*)d_in[5];
    const float* vw   = (const float*)d_in[6];
    const float* vb   = (const float*)d_in[7];
    const float* fc1w = (const float*)d_in[8];
    const float* fc1b = (const float*)d_in[9];
    const float* fc2w = (const float*)d_in[10];
    const float* fc2b = (const float*)d_in[11];
    const float* rw1  = (const float*)d_in[12];
    const float* rb1  = (const float*)d_in[13];
    const float* rw2  = (const float*)d_in[14];
    const float* rb2  = (const float*)d_in[15];

    float* out     = (float*)d_out;
    float* agg     = out;
    float* stacked = out + STACK_OFF;
    float* sparse  = out + SPARSE_OFF;

    float *gq, *gk, *gv, *gxo, *gh, *grh;
    cudaGetSymbolAddress((void**)&gq,  g_Q);
    cudaGetSymbolAddress((void**)&gk,  g_K);
    cudaGetSymbolAddress((void**)&gv,  g_V);
    cudaGetSymbolAddress((void**)&gxo, g_XO);
    cudaGetSymbolAddress((void**)&gh,  g_H);
    cudaGetSymbolAddress((void**)&grh, g_RH);

    const long WE = (long)C_ * C_;
    const long OE = (long)M_ * C_;

    cudaFuncSetAttribute(gemm_bf16x3_kernel, cudaFuncAttributeMaxDynamicSharedMemorySize, GSMEM);

    dim3 gg(C_ / BN, M_ / BM, E_);
    dim3 gr(C_ / FBN, M_ / FBM, 1);

    gemm_bf16x3_kernel<<<gg, 256, GSMEM>>>(x, 0, qw, WE, qb, C_, gq, OE, C_, nullptr, 0, 0.125f, 0);
    gemm_bf16x3_kernel<<<gg, 256, GSMEM>>>(x, 0, kw, WE, kb, C_, gk, OE, C_, nullptr, 0, 1.0f, 0);
    gemm_bf16x3_kernel<<<gg, 256, GSMEM>>>(x, 0, vw, WE, vb, C_, gv, OE, C_, nullptr, 0, 1.0f, 0);

    {
        int smem = 4 * 64 * APAD * sizeof(float) + 3 * 64 * sizeof(float);
        cudaFuncSetAttribute(attn_kernel, cudaFuncAttributeMaxDynamicSharedMemorySize, smem);
        dim3 ag(S_ / 64, H_, E_ * B_);
        attn_kernel<<<ag, 256, smem>>>(gq, gk, gv, mask, gxo);
    }

    gemm_bf16x3_kernel<<<gg, 256, GSMEM>>>(gxo, OE, fc1w, WE, fc1b, C_, gh, OE, C_, nullptr, 0, 1.0f, 1);
    gemm_bf16x3_kernel<<<gg, 256, GSMEM>>>(gh, OE, fc2w, WE, fc2b, C_, stacked, C_, E_ * C_, gxo, OE, 1.0f, 2);

    // Router in exact fp32 (top-2 selection is discontinuous — must match fp32)
    gemm_f32_kernel<<<gr, 256>>>(x, rw1, rb1, grh);
    router_kernel<<<(M_ * 32 + 255) / 256, 256>>>(grh, rw2, rb2, sparse);

    agg_kernel<<<(M_ * (C_ / 4) + 255) / 256, 256>>>(stacked, sparse, agg);
}

// round 8
// speedup vs baseline: 1.9500x; 1.2396x over previous
#include <cuda_runtime.h>
#include <cuda_bf16.h>
#include <math.h>
#include <stdint.h>

// Problem constants
#define B_ 8
#define S_ 512
#define C_ 512
#define H_ 8
#define D_ 64
#define E_ 6
#define M_ 4096          // B*S
#define RH_ 512
#define EPS_ 1e-8f

// d_out layout: aggregated (M*C), stacked (M*E*C), sparse (M*E)
#define AGG_ELEMS   (M_*C_)
#define STACK_ELEMS (M_*E_*C_)
#define STACK_OFF   (AGG_ELEMS)
#define SPARSE_OFF  (AGG_ELEMS + STACK_ELEMS)

// Scratch (device globals — no runtime allocation allowed)
__device__ float g_Q [E_*M_*C_];
__device__ float g_K [E_*M_*C_];
__device__ float g_V [E_*M_*C_];
__device__ float g_XO[E_*M_*C_];
__device__ float g_H [E_*M_*C_];
__device__ float g_RH[M_*RH_];

__device__ __forceinline__ float gelu_exact(float v) {
    return 0.5f * v * (1.0f + erff(v * 0.70710678118654752f));
}

__device__ __forceinline__ void bf16_split(float f, unsigned short& h, unsigned short& l) {
    __nv_bfloat16 bh = __float2bfloat16_rn(f);
    float r = f - __bfloat162float(bh);
    __nv_bfloat16 bl = __float2bfloat16_rn(r);
    h = __bfloat16_as_ushort(bh);
    l = __bfloat16_as_ushort(bl);
}

__device__ __forceinline__ uint32_t pack2(unsigned short lo16, unsigned short hi16) {
    return ((uint32_t)hi16 << 16) | (uint32_t)lo16;
}

__device__ __forceinline__ void mma_bf16(float4& d,
    uint32_t a0, uint32_t a1, uint32_t a2, uint32_t a3,
    uint32_t b0, uint32_t b1)
{
    asm volatile(
        "mma.sync.aligned.m16n8k16.row.col.f32.bf16.bf16.f32 "
        "{%0,%1,%2,%3}, {%4,%5,%6,%7}, {%8,%9}, {%0,%1,%2,%3};\n"
        : "+f"(d.x), "+f"(d.y), "+f"(d.z), "+f"(d.w)
        : "r"(a0), "r"(a1), "r"(a2), "r"(a3), "r"(b0), "r"(b1));
}

__device__ __forceinline__ uint32_t f2tf32(float v) {
    uint32_t r;
    asm("cvt.rna.tf32.f32 %0, %1;" : "=r"(r) : "f"(v));
    return r;
}

__device__ __forceinline__ void tf32_split(float f, uint32_t& h, uint32_t& l) {
    h = f2tf32(f);
    l = f2tf32(f - __uint_as_float(h));
}

__device__ __forceinline__ void mma_tf32(float4& d,
    uint32_t a0, uint32_t a1, uint32_t a2, uint32_t a3,
    uint32_t b0, uint32_t b1)
{
    asm volatile(
        "mma.sync.aligned.m16n8k8.row.col.f32.tf32.tf32.f32 "
        "{%0,%1,%2,%3}, {%4,%5,%6,%7}, {%8,%9}, {%0,%1,%2,%3};\n"
        : "+f"(d.x), "+f"(d.y), "+f"(d.z), "+f"(d.w)
        : "r"(a0), "r"(a1), "r"(a2), "r"(a3), "r"(b0), "r"(b1));
}

// ---------------------------------------------------------------------------
// Batched bf16x3 (split) tensor-core GEMM, fp32-class accuracy. (unchanged)
// ---------------------------------------------------------------------------
#define BM 128
#define BN 128
#define BK 32
#define KP 16
#define APITCH 20
#define BPITCH 136
#define AWORDS (BM*APITCH)   // 2560
#define BWORDS (KP*BPITCH)   // 2176
#define GSMEM  ((2*AWORDS + 2*BWORDS) * 2 * 4)  // 75776

__global__ __launch_bounds__(256) void gemm_bf16x3_kernel(
    const float* __restrict__ A,  long strideAe,
    const float* __restrict__ W,  long strideWe,
    const float* __restrict__ bias, long strideBe,
    float* __restrict__ out, long strideOe, int ldo,
    const float* __restrict__ res, long strideRe,
    float alpha, int mode)
{
    int z = blockIdx.z;
    A    += z * strideAe;
    W    += z * strideWe;
    bias += z * strideBe;
    out  += z * strideOe;
    const float* resz = res ? res + z * strideRe : nullptr;

    int m0 = blockIdx.y * BM;
    int n0 = blockIdx.x * BN;

    extern __shared__ uint32_t smw[];
    uint32_t* Ahi = smw;
    uint32_t* Alo = Ahi + 2 * AWORDS;
    uint32_t* Bhi = Alo + 2 * AWORDS;
    uint32_t* Blo = Bhi + 2 * BWORDS;

    int tid  = threadIdx.x;
    int lane = tid & 31;
    int warp = tid >> 5;
    int wm   = warp & 3;
    int wn   = warp >> 2;
    int g    = lane >> 2;
    int t    = lane & 3;

    int ar = tid >> 3;
    int ac = (tid & 7) << 2;
    const float* aptr = A + (long)(m0 + ar) * 512 + ac;
    int abase = ar * APITCH + (ac >> 1);

    const float* bptr = W + n0 + lane;

    float4 acc[2][8];
#pragma unroll
    for (int i = 0; i < 2; i++)
#pragma unroll
        for (int j = 0; j < 8; j++) acc[i][j] = make_float4(0.f, 0.f, 0.f, 0.f);

    auto store_tile = [&](int buf, const float4 av[4], const float bv[2][4][2]) {
        uint32_t* ah = Ahi + buf * AWORDS;
        uint32_t* al = Alo + buf * AWORDS;
#pragma unroll
        for (int i = 0; i < 4; i++) {
            unsigned short hx, lx, hy, ly, hz, lz, hw, lw;
            bf16_split(av[i].x, hx, lx);
            bf16_split(av[i].y, hy, ly);
            bf16_split(av[i].z, hz, lz);
            bf16_split(av[i].w, hw, lw);
            int a0 = abase + 32 * i * APITCH;
            ah[a0]     = pack2(hx, hy);
            ah[a0 + 1] = pack2(hz, hw);
            al[a0]     = pack2(lx, ly);
            al[a0 + 1] = pack2(lz, lw);
        }
        uint32_t* bh = Bhi + buf * BWORDS;
        uint32_t* bl = Blo + buf * BWORDS;
#pragma unroll
        for (int p = 0; p < 2; p++) {
            int kp = 2 * warp + p;
#pragma unroll
            for (int j = 0; j < 4; j++) {
                unsigned short h0, l0, h1, l1;
                bf16_split(bv[p][j][0], h0, l0);
                bf16_split(bv[p][j][1], h1, l1);
                int off = kp * BPITCH + lane + 32 * j;
                bh[off] = pack2(h0, h1);
                bl[off] = pack2(l0, l1);
            }
        }
    };

    {
        float4 av[4];
        float  bv[2][4][2];
#pragma unroll
        for (int i = 0; i < 4; i++)
            av[i] = *(const float4*)(aptr + (long)(32 * i) * 512);
#pragma unroll
        for (int p = 0; p < 2; p++)
#pragma unroll
            for (int j = 0; j < 4; j++)
#pragma unroll
                for (int s = 0; s < 2; s++)
                    bv[p][j][s] = bptr[(long)(4 * warp + 2 * p + s) * 512 + 32 * j];
        store_tile(0, av, bv);
    }
    __syncthreads();

    const int NT = 512 / BK;
    float4 pav[4];
    float  pbv[2][4][2];

    for (int kt = 0; kt < NT; kt++) {
        int cur = kt & 1;
        if (kt + 1 < NT) {
            const float* ap = aptr + (kt + 1) * BK;
#pragma unroll
            for (int i = 0; i < 4; i++)
                pav[i] = *(const float4*)(ap + (long)(32 * i) * 512);
#pragma unroll
            for (int p = 0; p < 2; p++)
#pragma unroll
                for (int j = 0; j < 4; j++)
#pragma unroll
                    for (int s = 0; s < 2; s++)
                        pbv[p][j][s] = bptr[(long)((kt + 1) * BK + 4 * warp + 2 * p + s) * 512 + 32 * j];
        }

        const uint32_t* ah = Ahi + cur * AWORDS;
        const uint32_t* al = Alo + cur * AWORDS;
        const uint32_t* bh = Bhi + cur * BWORDS;
        const uint32_t* bl = Blo + cur * BWORDS;

#pragma unroll
        for (int kk = 0; kk < 2; kk++) {
            uint32_t afh[2][4], afl[2][4];
#pragma unroll
            for (int mt = 0; mt < 2; mt++) {
                int row = wm * 32 + mt * 16 + g;
                int base = row * APITCH + kk * 8 + t;
                afh[mt][0] = ah[base];
                afh[mt][1] = ah[base + 8 * APITCH];
                afh[mt][2] = ah[base + 4];
                afh[mt][3] = ah[base + 8 * APITCH + 4];
                afl[mt][0] = al[base];
                afl[mt][1] = al[base + 8 * APITCH];
                afl[mt][2] = al[base + 4];
                afl[mt][3] = al[base + 8 * APITCH + 4];
            }
#pragma unroll
            for (int nt = 0; nt < 8; nt++) {
                int col = wn * 64 + nt * 8 + g;
                int bbase = (kk * 8 + t) * BPITCH + col;
                uint32_t bh0 = bh[bbase];
                uint32_t bh1 = bh[bbase + 4 * BPITCH];
                uint32_t bl0 = bl[bbase];
                uint32_t bl1 = bl[bbase + 4 * BPITCH];
#pragma unroll
                for (int mt = 0; mt < 2; mt++) {
                    mma_bf16(acc[mt][nt], afh[mt][0], afh[mt][1], afh[mt][2], afh[mt][3], bh0, bh1);
                    mma_bf16(acc[mt][nt], afh[mt][0], afh[mt][1], afh[mt][2], afh[mt][3], bl0, bl1);
                    mma_bf16(acc[mt][nt], afl[mt][0], afl[mt][1], afl[mt][2], afl[mt][3], bh0, bh1);
                }
            }
        }

        if (kt + 1 < NT) {
            store_tile(cur ^ 1, pav, pbv);
            __syncthreads();
        }
    }

#pragma unroll
    for (int mt = 0; mt < 2; mt++) {
        int R0 = m0 + wm * 32 + mt * 16 + g;
        int R1 = R0 + 8;
#pragma unroll
        for (int nt = 0; nt < 8; nt++) {
            int N0 = n0 + wn * 64 + nt * 8 + 2 * t;
            float b0 = bias[N0], b1 = bias[N0 + 1];
            float4 a = acc[mt][nt];
            float v0 = a.x + b0, v1 = a.y + b1, v2 = a.z + b0, v3 = a.w + b1;
            if (mode == 0)      { v0 *= alpha; v1 *= alpha; v2 *= alpha; v3 *= alpha; }
            else if (mode == 1) { v0 = gelu_exact(v0); v1 = gelu_exact(v1); v2 = gelu_exact(v2); v3 = gelu_exact(v3); }
            else {
                float2 r0 = *(const float2*)(resz + (long)R0 * 512 + N0);
                float2 r1 = *(const float2*)(resz + (long)R1 * 512 + N0);
                v0 += r0.x; v1 += r0.y; v2 += r1.x; v3 += r1.y;
            }
            *(float2*)(out + (long)R0 * ldo + N0) = make_float2(v0, v1);
            *(float2*)(out + (long)R1 * ldo + N0) = make_float2(v2, v3);
        }
    }
}

// ---------------------------------------------------------------------------
// tf32x3 GEMM (router rh path): fp32-faithful via tf32 hi/lo split, gelu epi.
// out[m,n] = gelu(sum_k A[m,k]*W[k,n] + bias[n]); sizes 4096x512x512.
// ---------------------------------------------------------------------------
#define RAW 2560   // 128*20
#define RBW 2176   // 16*136
#define RSMEM ((2*RAW + 2*RBW) * 2 * 4)   // 75776

__global__ __launch_bounds__(256) void gemm_tf32x3_kernel(
    const float* __restrict__ A, const float* __restrict__ W,
    const float* __restrict__ bias, float* __restrict__ out)
{
    int m0 = blockIdx.y * 128;
    int n0 = blockIdx.x * 128;

    extern __shared__ uint32_t rs[];
    uint32_t* Ah = rs;
    uint32_t* Al = Ah + 2 * RAW;
    uint32_t* Bh = Al + 2 * RAW;
    uint32_t* Bl = Bh + 2 * RBW;

    int tid = threadIdx.x, lane = tid & 31, warp = tid >> 5;
    int wm = warp & 3, wn = warp >> 2, g = lane >> 2, t = lane & 3;

    int ar = tid >> 2;              // 0..63
    int ak = (tid & 3) << 2;        // 0,4,8,12
    const float* aptr = A + (long)(m0 + ar) * 512 + ak;
    int bk = tid >> 5;              // 0..7
    int bn = (tid & 31) << 2;
    const float* bptr = W + (long)bk * 512 + n0 + bn;

    int as0 = ar * 20 + ak, as1 = (ar + 64) * 20 + ak;
    int bs0 = bk * 136 + bn, bs1 = (bk + 8) * 136 + bn;

    float4 acc[2][8];
#pragma unroll
    for (int i = 0; i < 2; i++)
#pragma unroll
        for (int j = 0; j < 8; j++) acc[i][j] = make_float4(0.f, 0.f, 0.f, 0.f);

    auto st = [&](int buf, float4 a0v, float4 a1v, float4 b0v, float4 b1v) {
        uint32_t* ah = Ah + buf * RAW;  uint32_t* al = Al + buf * RAW;
        uint32_t* bh = Bh + buf * RBW;  uint32_t* bl = Bl + buf * RBW;
        uint32_t h, l;
        tf32_split(a0v.x, h, l); ah[as0+0]=h; al[as0+0]=l;
        tf32_split(a0v.y, h, l); ah[as0+1]=h; al[as0+1]=l;
        tf32_split(a0v.z, h, l); ah[as0+2]=h; al[as0+2]=l;
        tf32_split(a0v.w, h, l); ah[as0+3]=h; al[as0+3]=l;
        tf32_split(a1v.x, h, l); ah[as1+0]=h; al[as1+0]=l;
        tf32_split(a1v.y, h, l); ah[as1+1]=h; al[as1+1]=l;
        tf32_split(a1v.z, h, l); ah[as1+2]=h; al[as1+2]=l;
        tf32_split(a1v.w, h, l); ah[as1+3]=h; al[as1+3]=l;
        tf32_split(b0v.x, h, l); bh[bs0+0]=h; bl[bs0+0]=l;
        tf32_split(b0v.y, h, l); bh[bs0+1]=h; bl[bs0+1]=l;
        tf32_split(b0v.z, h, l); bh[bs0+2]=h; bl[bs0+2]=l;
        tf32_split(b0v.w, h, l); bh[bs0+3]=h; bl[bs0+3]=l;
        tf32_split(b1v.x, h, l); bh[bs1+0]=h; bl[bs1+0]=l;
        tf32_split(b1v.y, h, l); bh[bs1+1]=h; bl[bs1+1]=l;
        tf32_split(b1v.z, h, l); bh[bs1+2]=h; bl[bs1+2]=l;
        tf32_split(b1v.w, h, l); bh[bs1+3]=h; bl[bs1+3]=l;
    };

    {
        float4 a0v = *(const float4*)(aptr);
        float4 a1v = *(const float4*)(aptr + 64 * 512);
        float4 b0v = *(const float4*)(bptr);
        float4 b1v = *(const float4*)(bptr + 8 * 512);
        st(0, a0v, a1v, b0v, b1v);
    }
    __syncthreads();

    float4 pa0, pa1, pb0, pb1;
    for (int kt = 0; kt < 32; kt++) {
        int cur = kt & 1;
        if (kt + 1 < 32) {
            const float* ap = aptr + (kt + 1) * 16;
            const float* bp = bptr + (long)(kt + 1) * 16 * 512;
            pa0 = *(const float4*)(ap);
            pa1 = *(const float4*)(ap + 64 * 512);
            pb0 = *(const float4*)(bp);
            pb1 = *(const float4*)(bp + 8 * 512);
        }

        const uint32_t* ah = Ah + cur * RAW;
        const uint32_t* al = Al + cur * RAW;
        const uint32_t* bh = Bh + cur * RBW;
        const uint32_t* bl = Bl + cur * RBW;

#pragma unroll
        for (int k8 = 0; k8 < 16; k8 += 8) {
            uint32_t afh[2][4], afl[2][4];
#pragma unroll
            for (int mt = 0; mt < 2; mt++) {
                int row = wm * 32 + mt * 16 + g;
                int base = row * 20 + k8 + t;
                afh[mt][0] = ah[base];
                afh[mt][1] = ah[base + 8 * 20];
                afh[mt][2] = ah[base + 4];
                afh[mt][3] = ah[base + 8 * 20 + 4];
                afl[mt][0] = al[base];
                afl[mt][1] = al[base + 8 * 20];
                afl[mt][2] = al[base + 4];
                afl[mt][3] = al[base + 8 * 20 + 4];
            }
#pragma unroll
            for (int nt = 0; nt < 8; nt++) {
                int col = wn * 64 + nt * 8 + g;
                uint32_t bh0 = bh[(k8 + t) * 136 + col];
                uint32_t bh1 = bh[(k8 + 4 + t) * 136 + col];
                uint32_t bl0 = bl[(k8 + t) * 136 + col];
                uint32_t bl1 = bl[(k8 + 4 + t) * 136 + col];
#pragma unroll
                for (int mt = 0; mt < 2; mt++) {
                    mma_tf32(acc[mt][nt], afh[mt][0], afh[mt][1], afh[mt][2], afh[mt][3], bh0, bh1);
                    mma_tf32(acc[mt][nt], afh[mt][0], afh[mt][1], afh[mt][2], afh[mt][3], bl0, bl1);
                    mma_tf32(acc[mt][nt], afl[mt][0], afl[mt][1], afl[mt][2], afl[mt][3], bh0, bh1);
                }
            }
        }

        if (kt + 1 < 32) {
            st(cur ^ 1, pa0, pa1, pb0, pb1);
            __syncthreads();
        }
    }

#pragma unroll
    for (int mt = 0; mt < 2; mt++) {
        int R0 = m0 + wm * 32 + mt * 16 + g;
        int R1 = R0 + 8;
#pragma unroll
        for (int nt = 0; nt < 8; nt++) {
            int N0 = n0 + wn * 64 + nt * 8 + 2 * t;
            float b0 = bias[N0], b1 = bias[N0 + 1];
            float4 a = acc[mt][nt];
            *(float2*)(out + (long)R0 * 512 + N0) =
                make_float2(gelu_exact(a.x + b0), gelu_exact(a.y + b1));
            *(float2*)(out + (long)R1 * 512 + N0) =
                make_float2(gelu_exact(a.z + b0), gelu_exact(a.w + b1));
        }
    }
}

// ---------------------------------------------------------------------------
// MMA flash attention: per (e,b,h), 64-query block, 64-key tiles, bf16x3 MMA
// for S=QK^T and O+=P·V, fp32 online softmax.
// ---------------------------------------------------------------------------
#define KP36 36    // [row][kpair] pitch for Q/K/P (32 kpairs + 4 pad): banks 4g+t, conflict-free
#define VP35 35    // [d][jpair] pitch for V^T: 2-way max on loads & stores
#define PSP  68    // Ps fp32 pitch
// smem words: 6*64*36 + 2*64*35 + 64*68 + 3*64 + 64 = 22912 -> 91648 bytes
#define ATT_SMEM (22912 * 4)

__global__ __launch_bounds__(256) void attn_mma_kernel(
    const float* __restrict__ Q, const float* __restrict__ K,
    const float* __restrict__ V, const int* __restrict__ mask,
    float* __restrict__ XO)
{
    extern __shared__ uint32_t smu[];
    uint32_t* Qh = smu;
    uint32_t* Ql = Qh + 64 * KP36;
    uint32_t* Kh = Ql + 64 * KP36;
    uint32_t* Kl = Kh + 64 * KP36;
    uint32_t* Ph = Kl + 64 * KP36;
    uint32_t* Pl = Ph + 64 * KP36;
    uint32_t* Vh = Pl + 64 * KP36;
    uint32_t* Vl = Vh + 64 * VP35;
    float* Ps    = (float*)(Vl + 64 * VP35);
    float* rowm  = Ps + 64 * PSP;
    float* rowl  = rowm + 64;
    float* rowsc = rowl + 64;
    int*   ms    = (int*)(rowsc + 64);

    int tid = threadIdx.x;
    int lane = tid & 31, warp = tid >> 5;
    int wm = warp & 3, wn = warp >> 2;
    int g = lane >> 2, t = lane & 3;

    int h  = blockIdx.y;
    int eb = blockIdx.z;
    int b  = eb & (B_ - 1);
    int q0 = blockIdx.x * 64;

    const float* Qp = Q + (long)eb * S_ * C_ + h * 64;
    const float* Kp = K + (long)eb * S_ * C_ + h * 64;
    const float* Vp = V + (long)eb * S_ * C_ + h * 64;
    float*       Op = XO + (long)eb * S_ * C_ + h * 64;
    const int* mrow = mask + b * 3 * S_;

    // Load Q once: [q][dpair] split bf16
#pragma unroll
    for (int it = 0; it < 4; it++) {
        int lin = tid + it * 256;
        int r   = lin >> 4;
        int c4  = (lin & 15) << 2;
        float4 v = *(const float4*)(Qp + (long)(q0 + r) * C_ + c4);
        unsigned short hx, lx, hy, ly, hz, lz, hw, lw;
        bf16_split(v.x, hx, lx); bf16_split(v.y, hy, ly);
        bf16_split(v.z, hz, lz); bf16_split(v.w, hw, lw);
        int w0 = r * KP36 + (c4 >> 1);
        Qh[w0] = pack2(hx, hy); Qh[w0 + 1] = pack2(hz, hw);
        Ql[w0] = pack2(lx, ly); Ql[w0 + 1] = pack2(lz, lw);
    }
    if (tid < 64) { rowm[tid] = -1e30f; rowl[tid] = 0.f; }

    int m0r = wm * 16 + g;
    int m1r = m0r + 8;

    float4 ofr[4];
#pragma unroll
    for (int nt = 0; nt < 4; nt++) ofr[nt] = make_float4(0.f, 0.f, 0.f, 0.f);

    for (int t0 = 0; t0 < S_; t0 += 64) {
        __syncthreads();
        // Load K [j][dpair] and V transposed [d][jpair]
#pragma unroll
        for (int it = 0; it < 4; it++) {
            int lin = tid + it * 256;
            int r   = lin >> 4;
            int c4  = (lin & 15) << 2;
            float4 kv = *(const float4*)(Kp + (long)(t0 + r) * C_ + c4);
            unsigned short hx, lx, hy, ly, hz, lz, hw, lw;
            bf16_split(kv.x, hx, lx); bf16_split(kv.y, hy, ly);
            bf16_split(kv.z, hz, lz); bf16_split(kv.w, hw, lw);
            int w0 = r * KP36 + (c4 >> 1);
            Kh[w0] = pack2(hx, hy); Kh[w0 + 1] = pack2(hz, hw);
            Kl[w0] = pack2(lx, ly); Kl[w0 + 1] = pack2(lz, lw);

            float4 vv = *(const float4*)(Vp + (long)(t0 + r) * C_ + c4);
            unsigned short vh0, vl0, vh1, vl1, vh2, vl2, vh3, vl3;
            bf16_split(vv.x, vh0, vl0); bf16_split(vv.y, vh1, vl1);
            bf16_split(vv.z, vh2, vl2); bf16_split(vv.w, vh3, vl3);
            uint32_t H01 = pack2(vh0, vh1), H23 = pack2(vh2, vh3);
            uint32_t L01 = pack2(vl0, vl1), L23 = pack2(vl2, vl3);
            // lanes 0-15 have even j=r, lanes 16-31 odd; pair via shfl^16
            uint32_t pH01 = __shfl_xor_sync(0xffffffffu, H01, 16);
            uint32_t pH23 = __shfl_xor_sync(0xffffffffu, H23, 16);
            uint32_t pL01 = __shfl_xor_sync(0xffffffffu, L01, 16);
            uint32_t pL23 = __shfl_xor_sync(0xffffffffu, L23, 16);
            int jp = r >> 1;
            if (lane < 16) {  // even j: mine is low half
                Vh[(c4 + 0) * VP35 + jp] = (H01 & 0xFFFFu) | (pH01 << 16);
                Vh[(c4 + 1) * VP35 + jp] = (H01 >> 16)     | (pH01 & 0xFFFF0000u);
                Vl[(c4 + 0) * VP35 + jp] = (L01 & 0xFFFFu) | (pL01 << 16);
                Vl[(c4 + 1) * VP35 + jp] = (L01 >> 16)     | (pL01 & 0xFFFF0000u);
            } else {          // odd j: mine is high half
                Vh[(c4 + 2) * VP35 + jp] = (pH23 & 0xFFFFu) | (H23 << 16);
                Vh[(c4 + 3) * VP35 + jp] = (pH23 >> 16)     | (H23 & 0xFFFF0000u);
                Vl[(c4 + 2) * VP35 + jp] = (pL23 & 0xFFFFu) | (L23 << 16);
                Vl[(c4 + 3) * VP35 + jp] = (pL23 >> 16)     | (L23 & 0xFFFF0000u);
            }
        }
        if (tid < 64) ms[tid] = mrow[t0 + tid];
        __syncthreads();

        // S = Q @ K^T (bf16x3)
        float4 sfr[4];
#pragma unroll
        for (int nt = 0; nt < 4; nt++) sfr[nt] = make_float4(0.f, 0.f, 0.f, 0.f);
#pragma unroll
        for (int kk = 0; kk < 4; kk++) {
            int a0 = m0r * KP36 + kk * 8 + t;
            int a1 = m1r * KP36 + kk * 8 + t;
            uint32_t ah0 = Qh[a0], ah1 = Qh[a1], ah2 = Qh[a0 + 4], ah3 = Qh[a1 + 4];
            uint32_t al0 = Ql[a0], al1 = Ql[a1], al2 = Ql[a0 + 4], al3 = Ql[a1 + 4];
#pragma unroll
            for (int nt = 0; nt < 4; nt++) {
                int j  = wn * 32 + nt * 8 + g;
                int bo = j * KP36 + kk * 8 + t;
                uint32_t bh0 = Kh[bo], bh1 = Kh[bo + 4];
                uint32_t bl0 = Kl[bo], bl1 = Kl[bo + 4];
                mma_bf16(sfr[nt], ah0, ah1, ah2, ah3, bh0, bh1);
                mma_bf16(sfr[nt], ah0, ah1, ah2, ah3, bl0, bl1);
                mma_bf16(sfr[nt], al0, al1, al2, al3, bh0, bh1);
            }
        }
        // mask + write S to Ps
#pragma unroll
        for (int nt = 0; nt < 4; nt++) {
            int c0 = wn * 32 + nt * 8 + 2 * t;
            bool ok0 = ms[c0] != 0, ok1 = ms[c0 + 1] != 0;
            Ps[m0r * PSP + c0]     = ok0 ? sfr[nt].x : -1e30f;
            Ps[m0r * PSP + c0 + 1] = ok1 ? sfr[nt].y : -1e30f;
            Ps[m1r * PSP + c0]     = ok0 ? sfr[nt].z : -1e30f;
            Ps[m1r * PSP + c0 + 1] = ok1 ? sfr[nt].w : -1e30f;
        }
        __syncthreads();

        // Online softmax; write P as split bf16 [q][jpair]
        {
            int row = tid >> 2, quad = tid & 3;
            float p[16];
            const float* pr = &Ps[row * PSP + quad * 16];
            float mx = -1e30f;
#pragma unroll
            for (int t4 = 0; t4 < 4; t4++) {
                float4 v = *(const float4*)(pr + t4 * 4);
                p[t4*4+0] = v.x; p[t4*4+1] = v.y; p[t4*4+2] = v.z; p[t4*4+3] = v.w;
                mx = fmaxf(mx, fmaxf(fmaxf(v.x, v.y), fmaxf(v.z, v.w)));
            }
            mx = fmaxf(mx, __shfl_xor_sync(0xffffffffu, mx, 1));
            mx = fmaxf(mx, __shfl_xor_sync(0xffffffffu, mx, 2));
            float oldm = rowm[row];
            float newm = fmaxf(oldm, mx);
            float sum = 0.f;
#pragma unroll
            for (int tt = 0; tt < 16; tt++) {
                float e = __expf(p[tt] - newm);
                p[tt] = e;
                sum += e;
            }
            sum += __shfl_xor_sync(0xffffffffu, sum, 1);
            sum += __shfl_xor_sync(0xffffffffu, sum, 2);
            float scale = __expf(oldm - newm);
            __nv_bfloat16* phb = (__nv_bfloat16*)Ph;
            __nv_bfloat16* plb = (__nv_bfloat16*)Pl;
#pragma unroll
            for (int tt = 0; tt < 16; tt++) {
                int j = quad * 16 + tt;
                float f = p[tt];
                __nv_bfloat16 bh = __float2bfloat16_rn(f);
                float rl = f - __bfloat162float(bh);
                phb[row * (2 * KP36) + j] = bh;
                plb[row * (2 * KP36) + j] = __float2bfloat16_rn(rl);
            }
            if (quad == 0) {
                rowl[row] = rowl[row] * scale + sum;
                rowm[row] = newm;
                rowsc[row] = scale;
            }
        }
        __syncthreads();

        // O = O*scale + P @ V (bf16x3), B = V^T fragments
        float sc0 = rowsc[m0r], sc1 = rowsc[m1r];
#pragma unroll
        for (int nt = 0; nt < 4; nt++) {
            ofr[nt].x *= sc0; ofr[nt].y *= sc0;
            ofr[nt].z *= sc1; ofr[nt].w *= sc1;
        }
#pragma unroll
        for (int kk = 0; kk < 4; kk++) {
            int a0 = m0r * KP36 + kk * 8 + t;
            int a1 = m1r * KP36 + kk * 8 + t;
            uint32_t ah0 = Ph[a0], ah1 = Ph[a1], ah2 = Ph[a0 + 4], ah3 = Ph[a1 + 4];
            uint32_t al0 = Pl[a0], al1 = Pl[a1], al2 = Pl[a0 + 4], al3 = Pl[a1 + 4];
#pragma unroll
            for (int nt = 0; nt < 4; nt++) {
                int d  = wn * 32 + nt * 8 + g;
                int bo = d * VP35 + kk * 8 + t;
                uint32_t bh0 = Vh[bo], bh1 = Vh[bo + 4];
                uint32_t bl0 = Vl[bo], bl1 = Vl[bo + 4];
                mma_bf16(ofr[nt], ah0, ah1, ah2, ah3, bh0, bh1);
                mma_bf16(ofr[nt], ah0, ah1, ah2, ah3, bl0, bl1);
                mma_bf16(ofr[nt], al0, al1, al2, al3, bh0, bh1);
            }
        }
    }

    // Final normalize + write
    float l0 = rowl[m0r], l1 = rowl[m1r];
    float inv0 = (l0 > 0.f) ? (1.f / l0) : 0.f;
    float inv1 = (l1 > 0.f) ? (1.f / l1) : 0.f;
#pragma unroll
    for (int nt = 0; nt < 4; nt++) {
        int c0 = wn * 32 + nt * 8 + 2 * t;
        *(float2*)(Op + (long)(q0 + m0r) * C_ + c0) =
            make_float2(ofr[nt].x * inv0, ofr[nt].y * inv0);
        *(float2*)(Op + (long)(q0 + m1r) * C_ + c0) =
            make_float2(ofr[nt].z * inv1, ofr[nt].w * inv1);
    }
}

// ---------------------------------------------------------------------------
// Router: logits + softmax + top-2 (strict >), renormalize. One warp/token.
// ---------------------------------------------------------------------------
__global__ __launch_bounds__(256) void router_kernel(
    const float* __restrict__ rh, const float* __restrict__ rw2,
    const float* __restrict__ rb2, float* __restrict__ sparse)
{
    int gwarp = (blockIdx.x * blockDim.x + threadIdx.x) >> 5;
    int lane  = threadIdx.x & 31;
    if (gwarp >= M_) return;

    const float* r = rh + (long)gwarp * RH_;
    float acc[E_];
#pragma unroll
    for (int e = 0; e < E_; e++) acc[e] = 0.f;
    for (int hh = lane; hh < RH_; hh += 32) {
        float xv = r[hh];
        const float* w = rw2 + hh * E_;
#pragma unroll
        for (int e = 0; e < E_; e++) acc[e] += xv * w[e];
    }
#pragma unroll
    for (int off = 16; off > 0; off >>= 1)
#pragma unroll
        for (int e = 0; e < E_; e++)
            acc[e] += __shfl_xor_sync(0xffffffffu, acc[e], off);

    if (lane == 0) {
        float lg[E_];
        float mx = -1e30f;
#pragma unroll
        for (int e = 0; e < E_; e++) { lg[e] = acc[e] + rb2[e]; mx = fmaxf(mx, lg[e]); }
        float sum = 0.f;
#pragma unroll
        for (int e = 0; e < E_; e++) { lg[e] = __expf(lg[e] - mx); sum += lg[e]; }
        float inv = 1.f / sum;
#pragma unroll
        for (int e = 0; e < E_; e++) lg[e] *= inv;
        int i1 = 0;
#pragma unroll
        for (int e = 1; e < E_; e++) if (lg[e] > lg[i1]) i1 = e;
        int i2 = (i1 == 0) ? 1 : 0;
#pragma unroll
        for (int e = 0; e < E_; e++) if (e != i1 && lg[e] > lg[i2]) i2 = e;
        float denom = fmaxf(lg[i1] + lg[i2], EPS_);
        float outv[E_];
#pragma unroll
        for (int e = 0; e < E_; e++) outv[e] = 0.f;
        outv[i1] = lg[i1] / denom;
        outv[i2] = lg[i2] / denom;
        float* o = sparse + (long)gwarp * E_;
#pragma unroll
        for (int e = 0; e < E_; e++) o[e] = outv[e];
    }
}

// ---------------------------------------------------------------------------
// Aggregation: agg[m,c] = sum_e sparse[m,e] * stacked[m,e,c]
// ---------------------------------------------------------------------------
__global__ __launch_bounds__(256) void agg_kernel(
    const float* __restrict__ stacked, const float* __restrict__ sparse,
    float* __restrict__ agg)
{
    int idx = blockIdx.x * blockDim.x + threadIdx.x;
    if (idx >= M_ * (C_ / 4)) return;
    int m  = idx >> 7;
    int c  = (idx & 127) << 2;
    const float* sp = sparse + (long)m * E_;
    float w[E_];
#pragma unroll
    for (int e = 0; e < E_; e++) w[e] = sp[e];
    float4 a = {0.f, 0.f, 0.f, 0.f};
#pragma unroll
    for (int e = 0; e < E_; e++) {
        float4 v = *(const float4*)(stacked + ((long)m * E_ + e) * C_ + c);
        a.x += w[e] * v.x; a.y += w[e] * v.y; a.z += w[e] * v.z; a.w += w[e] * v.w;
    }
    *(float4*)(agg + (long)m * C_ + c) = a;
}

// ---------------------------------------------------------------------------
// Launch
// ---------------------------------------------------------------------------
extern "C" void kernel_launch(void* const* d_in, const int* in_sizes, int n_in,
                              void* d_out, int out_size)
{
    const float* x    = (const float*)d_in[0];
    const int*   mask = (const int*)d_in[1];
    const float* qw   = (const float*)d_in[2];
    const float* qb   = (const float*)d_in[3];
    const float* kw   = (const float*)d_in[4];
    const float* kb   = (const float*)d_in[5];
    const float* vw   = (const float*)d_in[6];
    const float* vb   = (const float*)d_in[7];
    const float* fc1w = (const float*)d_in[8];
    const float* fc1b = (const float*)d_in[9];
    const float* fc2w = (const float*)d_in[10];
    const float* fc2b = (const float*)d_in[11];
    const float* rw1  = (const float*)d_in[12];
    const float* rb1  = (const float*)d_in[13];
    const float* rw2  = (const float*)d_in[14];
    const float* rb2  = (const float*)d_in[15];

    float* out     = (float*)d_out;
    float* agg     = out;
    float* stacked = out + STACK_OFF;
    float* sparse  = out + SPARSE_OFF;

    float *gq, *gk, *gv, *gxo, *gh, *grh;
    cudaGetSymbolAddress((void**)&gq,  g_Q);
    cudaGetSymbolAddress((void**)&gk,  g_K);
    cudaGetSymbolAddress((void**)&gv,  g_V);
    cudaGetSymbolAddress((void**)&gxo, g_XO);
    cudaGetSymbolAddress((void**)&gh,  g_H);
    cudaGetSymbolAddress((void**)&grh, g_RH);

    const long WE = (long)C_ * C_;
    const long OE = (long)M_ * C_;

    cudaFuncSetAttribute(gemm_bf16x3_kernel, cudaFuncAttributeMaxDynamicSharedMemorySize, GSMEM);
    cudaFuncSetAttribute(gemm_tf32x3_kernel, cudaFuncAttributeMaxDynamicSharedMemorySize, RSMEM);
    cudaFuncSetAttribute(attn_mma_kernel,    cudaFuncAttributeMaxDynamicSharedMemorySize, ATT_SMEM);

    dim3 gg(C_ / BN, M_ / BM, E_);
    dim3 gr(C_ / 128, M_ / 128, 1);

    gemm_bf16x3_kernel<<<gg, 256, GSMEM>>>(x, 0, qw, WE, qb, C_, gq, OE, C_, nullptr, 0, 0.125f, 0);
    gemm_bf16x3_kernel<<<gg, 256, GSMEM>>>(x, 0, kw, WE, kb, C_, gk, OE, C_, nullptr, 0, 1.0f, 0);
    gemm_bf16x3_kernel<<<gg, 256, GSMEM>>>(x, 0, vw, WE, vb, C_, gv, OE, C_, nullptr, 0, 1.0f, 0);

    {
        dim3 ag(S_ / 64, H_, E_ * B_);
        attn_mma_kernel<<<ag, 256, ATT_SMEM>>>(gq, gk, gv, mask, gxo);
    }

    gemm_bf16x3_kernel<<<gg, 256, GSMEM>>>(gxo, OE, fc1w, WE, fc1b, C_, gh, OE, C_, nullptr, 0, 1.0f, 1);
    gemm_bf16x3_kernel<<<gg, 256, GSMEM>>>(gh, OE, fc2w, WE, fc2b, C_, stacked, C_, E_ * C_, gxo, OE, 1.0f, 2);

    // Router: rh in tf32x3 (error ~2^-22 — selection-safe), then fp32 top-2
    gemm_tf32x3_kernel<<<gr, 256, RSMEM>>>(x, rw1, rb1, grh);
    router_kernel<<<(M_ * 32 + 255) / 256, 256>>>(grh, rw2, rb2, sparse);

    agg_kernel<<<(M_ * (C_ / 4) + 255) / 256, 256>>>(stacked, sparse, agg);
}

// round 12
// speedup vs baseline: 2.1451x; 1.1000x over previous
#include <cuda_runtime.h>
#include <cuda_bf16.h>
#include <math.h>
#include <stdint.h>

// Problem constants
#define B_ 8
#define S_ 512
#define C_ 512
#define H_ 8
#define D_ 64
#define E_ 6
#define M_ 4096          // B*S
#define RH_ 512
#define EPS_ 1e-8f

#define AGG_ELEMS   (M_*C_)
#define STACK_ELEMS (M_*E_*C_)
#define STACK_OFF   (AGG_ELEMS)
#define SPARSE_OFF  (AGG_ELEMS + STACK_ELEMS)

// Packed split-bf16 planes: word = (bf16 lo16 = elem0, bf16 hi16 = elem1)
#define XPW  (M_*256)            // x plane words
#define WPW  (30*256*512)        // 5 sets x 6 experts, [z][kp][n]
#define TPE  (M_*256)            // per-expert activation plane words
#define TPW  (E_*TPE)

__device__ uint32_t g_Xh[XPW],  g_Xl[XPW];
__device__ uint32_t g_Wph[WPW], g_Wpl[WPW];
__device__ uint32_t g_Qph[TPW], g_Qpl[TPW];
__device__ uint32_t g_Kph[TPW], g_Kpl[TPW];
__device__ uint32_t g_Vph[TPW], g_Vpl[TPW];
__device__ uint32_t g_XOph[TPW], g_XOpl[TPW];
__device__ uint32_t g_Hph[TPW], g_Hpl[TPW];
__device__ float g_XO[E_*M_*C_];
__device__ float g_RH[M_*RH_];

__device__ __forceinline__ float gelu_exact(float v) {
    return 0.5f * v * (1.0f + erff(v * 0.70710678118654752f));
}

__device__ __forceinline__ void bf16_split(float f, unsigned short& h, unsigned short& l) {
    __nv_bfloat16 bh = __float2bfloat16_rn(f);
    float r = f - __bfloat162float(bh);
    __nv_bfloat16 bl = __float2bfloat16_rn(r);
    h = __bfloat16_as_ushort(bh);
    l = __bfloat16_as_ushort(bl);
}

__device__ __forceinline__ uint32_t pack2(unsigned short lo16, unsigned short hi16) {
    return ((uint32_t)hi16 << 16) | (uint32_t)lo16;
}

__device__ __forceinline__ void split_pair(float v0, float v1, uint32_t& hw, uint32_t& lw) {
    unsigned short h0, l0, h1, l1;
    bf16_split(v0, h0, l0);
    bf16_split(v1, h1, l1);
    hw = pack2(h0, h1);
    lw = pack2(l0, l1);
}

__device__ __forceinline__ void mma_bf16(float4& d,
    uint32_t a0, uint32_t a1, uint32_t a2, uint32_t a3,
    uint32_t b0, uint32_t b1)
{
    asm volatile(
        "mma.sync.aligned.m16n8k16.row.col.f32.bf16.bf16.f32 "
        "{%0,%1,%2,%3}, {%4,%5,%6,%7}, {%8,%9}, {%0,%1,%2,%3};\n"
        : "+f"(d.x), "+f"(d.y), "+f"(d.z), "+f"(d.w)
        : "r"(a0), "r"(a1), "r"(a2), "r"(a3), "r"(b0), "r"(b1));
}

__device__ __forceinline__ uint32_t f2tf32(float v) {
    uint32_t r;
    asm("cvt.rna.tf32.f32 %0, %1;" : "=r"(r) : "f"(v));
    return r;
}

__device__ __forceinline__ void tf32_split(float f, uint32_t& h, uint32_t& l) {
    h = f2tf32(f);
    l = f2tf32(f - __uint_as_float(h));
}

__device__ __forceinline__ void mma_tf32(float4& d,
    uint32_t a0, uint32_t a1, uint32_t a2, uint32_t a3,
    uint32_t b0, uint32_t b1)
{
    asm volatile(
        "mma.sync.aligned.m16n8k8.row.col.f32.tf32.tf32.f32 "
        "{%0,%1,%2,%3}, {%4,%5,%6,%7}, {%8,%9}, {%0,%1,%2,%3};\n"
        : "+f"(d.x), "+f"(d.y), "+f"(d.z), "+f"(d.w)
        : "r"(a0), "r"(a1), "r"(a2), "r"(a3), "r"(b0), "r"(b1));
}

// ---------------------------------------------------------------------------
// Prep kernels: split fp32 -> packed bf16 hi/lo planes
// ---------------------------------------------------------------------------
__global__ __launch_bounds__(256) void split_x_kernel(
    const float* __restrict__ x, uint32_t* __restrict__ xh, uint32_t* __restrict__ xl)
{
    int idx = blockIdx.x * 256 + threadIdx.x;
    if (idx >= XPW) return;
    float2 v = *(const float2*)(x + 2 * (long)idx);
    uint32_t hw, lw;
    split_pair(v.x, v.y, hw, lw);
    xh[idx] = hw; xl[idx] = lw;
}

__global__ __launch_bounds__(256) void split_w_kernel(
    const float* __restrict__ qw, const float* __restrict__ kw,
    const float* __restrict__ vw, const float* __restrict__ fc1w,
    const float* __restrict__ fc2w,
    uint32_t* __restrict__ wh, uint32_t* __restrict__ wl)
{
    int idx = blockIdx.x * 256 + threadIdx.x;
    if (idx >= WPW) return;
    int z   = idx >> 17;          // 131072 words per matrix
    int rem = idx & 131071;
    int kp  = rem >> 9;
    int n   = rem & 511;
    int set = z / 6, e = z - set * 6;
    const float* base = set == 0 ? qw : set == 1 ? kw : set == 2 ? vw : set == 3 ? fc1w : fc2w;
    const float* src = base + (long)e * 262144 + (long)(2 * kp) * 512 + n;
    uint32_t hw, lw;
    split_pair(src[0], src[512], hw, lw);
    wh[idx] = hw; wl[idx] = lw;
}

// ---------------------------------------------------------------------------
// Packed bf16x3 GEMM mainloop: A-planes [m][kp] (lda 256w), B-planes [kp][n] (ldb 512w)
// Tile 128x128x32 (16 kpairs). 256 threads = 8 warps of 32x64.
// ---------------------------------------------------------------------------
#define GSMEM ((2*2560 + 2*2560 + 2*2176 + 2*2176) * 4)  // 75776 bytes

__device__ __forceinline__ void packed_main(
    const uint32_t* __restrict__ Ah, const uint32_t* __restrict__ Al,
    const uint32_t* __restrict__ Bh, const uint32_t* __restrict__ Bl,
    int m0, int n0, float4 (&acc)[2][8])
{
    extern __shared__ uint32_t smw[];
    uint32_t* sAh = smw;                 // [2][2560]  pitch 20
    uint32_t* sAl = sAh + 2 * 2560;
    uint32_t* sBh = sAl + 2 * 2560;      // [2][2176]  pitch 136
    uint32_t* sBl = sBh + 2 * 2176;

    int tid = threadIdx.x, lane = tid & 31, warp = tid >> 5;
    int wm = warp & 3, wn = warp >> 2, g = lane >> 2, t = lane & 3;

    int ar = tid >> 2, kq = (tid & 3) << 2;
    const uint32_t* aph = Ah + (long)(m0 + ar) * 256 + kq;
    const uint32_t* apl = Al + (long)(m0 + ar) * 256 + kq;
    int br = tid >> 5, nq = (tid & 31) << 2;
    const uint32_t* bph = Bh + (long)br * 512 + n0 + nq;
    const uint32_t* bpl = Bl + (long)br * 512 + n0 + nq;

    int as0 = ar * 20 + kq, as1 = (ar + 64) * 20 + kq;
    int bs0 = br * 136 + nq, bs1 = (br + 8) * 136 + nq;

#pragma unroll
    for (int i = 0; i < 2; i++)
#pragma unroll
        for (int j = 0; j < 8; j++) acc[i][j] = make_float4(0.f, 0.f, 0.f, 0.f);

    uint4 ah0, ah1, al0, al1, bh0u, bh1u, bl0u, bl1u;

    // preload tile 0
    ah0  = *(const uint4*)(aph);
    ah1  = *(const uint4*)(aph + 64 * 256);
    al0  = *(const uint4*)(apl);
    al1  = *(const uint4*)(apl + 64 * 256);
    bh0u = *(const uint4*)(bph);
    bh1u = *(const uint4*)(bph + 8 * 512);
    bl0u = *(const uint4*)(bpl);
    bl1u = *(const uint4*)(bpl + 8 * 512);
    *(uint4*)(sAh + as0) = ah0;  *(uint4*)(sAh + as1) = ah1;
    *(uint4*)(sAl + as0) = al0;  *(uint4*)(sAl + as1) = al1;
    *(uint4*)(sBh + bs0) = bh0u; *(uint4*)(sBh + bs1) = bh1u;
    *(uint4*)(sBl + bs0) = bl0u; *(uint4*)(sBl + bs1) = bl1u;
    __syncthreads();

    const int NT = 16;   // 512 / 32
    for (int kt = 0; kt < NT; kt++) {
        int cur = kt & 1;
        if (kt + 1 < NT) {
            int ko = (kt + 1) * 16;
            ah0  = *(const uint4*)(aph + ko);
            ah1  = *(const uint4*)(aph + 64 * 256 + ko);
            al0  = *(const uint4*)(apl + ko);
            al1  = *(const uint4*)(apl + 64 * 256 + ko);
            bh0u = *(const uint4*)(bph + (long)ko * 512);
            bh1u = *(const uint4*)(bph + (long)(ko + 8) * 512);
            bl0u = *(const uint4*)(bpl + (long)ko * 512);
            bl1u = *(const uint4*)(bpl + (long)(ko + 8) * 512);
        }

        const uint32_t* ah = sAh + cur * 2560;
        const uint32_t* al = sAl + cur * 2560;
        const uint32_t* bh = sBh + cur * 2176;
        const uint32_t* bl = sBl + cur * 2176;

#pragma unroll
        for (int kk = 0; kk < 2; kk++) {
            uint32_t afh[2][4], afl[2][4];
#pragma unroll
            for (int mt = 0; mt < 2; mt++) {
                int row = wm * 32 + mt * 16 + g;
                int base = row * 20 + kk * 8 + t;
                afh[mt][0] = ah[base];
                afh[mt][1] = ah[base + 8 * 20];
                afh[mt][2] = ah[base + 4];
                afh[mt][3] = ah[base + 8 * 20 + 4];
                afl[mt][0] = al[base];
                afl[mt][1] = al[base + 8 * 20];
                afl[mt][2] = al[base + 4];
                afl[mt][3] = al[base + 8 * 20 + 4];
            }
#pragma unroll
            for (int nt = 0; nt < 8; nt++) {
                int col = wn * 64 + nt * 8 + g;
                int bbase = (kk * 8 + t) * 136 + col;
                uint32_t bh0 = bh[bbase];
                uint32_t bh1 = bh[bbase + 4 * 136];
                uint32_t bl0 = bl[bbase];
                uint32_t bl1 = bl[bbase + 4 * 136];
#pragma unroll
                for (int mt = 0; mt < 2; mt++) {
                    mma_bf16(acc[mt][nt], afh[mt][0], afh[mt][1], afh[mt][2], afh[mt][3], bh0, bh1);
                    mma_bf16(acc[mt][nt], afh[mt][0], afh[mt][1], afh[mt][2], afh[mt][3], bl0, bl1);
                    mma_bf16(acc[mt][nt], afl[mt][0], afl[mt][1], afl[mt][2], afl[mt][3], bh0, bh1);
                }
            }
        }

        if (kt + 1 < NT) {
            int nxt = cur ^ 1;
            *(uint4*)(sAh + nxt * 2560 + as0) = ah0;
            *(uint4*)(sAh + nxt * 2560 + as1) = ah1;
            *(uint4*)(sAl + nxt * 2560 + as0) = al0;
            *(uint4*)(sAl + nxt * 2560 + as1) = al1;
            *(uint4*)(sBh + nxt * 2176 + bs0) = bh0u;
            *(uint4*)(sBh + nxt * 2176 + bs1) = bh1u;
            *(uint4*)(sBl + nxt * 2176 + bs0) = bl0u;
            *(uint4*)(sBl + nxt * 2176 + bs1) = bl1u;
            __syncthreads();
        }
    }
}

// Fused QKV: z = set*6 + e, set in {0:Q,1:K,2:V}
__global__ __launch_bounds__(256) void qkv_packed_kernel(
    const uint32_t* __restrict__ Xh, const uint32_t* __restrict__ Xl,
    const uint32_t* __restrict__ Wh, const uint32_t* __restrict__ Wl,
    const float* __restrict__ qb, const float* __restrict__ kb, const float* __restrict__ vb,
    uint32_t* __restrict__ Qh, uint32_t* __restrict__ Ql,
    uint32_t* __restrict__ Kh, uint32_t* __restrict__ Kl,
    uint32_t* __restrict__ Vh, uint32_t* __restrict__ Vl)
{
    int z = blockIdx.z;
    int set = z / 6, e = z - set * 6;
    const float* bias = (set == 0 ? qb : set == 1 ? kb : vb) + e * C_;
    float alpha = (set == 0) ? 0.125f : 1.0f;
    uint32_t* Oh = (set == 0 ? Qh : set == 1 ? Kh : Vh) + (long)e * TPE;
    uint32_t* Ol = (set == 0 ? Ql : set == 1 ? Kl : Vl) + (long)e * TPE;

    int m0 = blockIdx.y * 128, n0 = blockIdx.x * 128;
    float4 acc[2][8];
    packed_main(Xh, Xl, Wh + (long)z * 131072, Wl + (long)z * 131072, m0, n0, acc);

    int lane = threadIdx.x & 31, warp = threadIdx.x >> 5;
    int wm = warp & 3, wn = warp >> 2, g = lane >> 2, t = lane & 3;
#pragma unroll
    for (int mt = 0; mt < 2; mt++) {
        int R0 = m0 + wm * 32 + mt * 16 + g;
        int R1 = R0 + 8;
#pragma unroll
        for (int nt = 0; nt < 8; nt++) {
            int N0 = n0 + wn * 64 + nt * 8 + 2 * t;
            float b0 = bias[N0], b1 = bias[N0 + 1];
            float4 a = acc[mt][nt];
            float v0 = (a.x + b0) * alpha, v1 = (a.y + b1) * alpha;
            float v2 = (a.z + b0) * alpha, v3 = (a.w + b1) * alpha;
            uint32_t hw, lw;
            split_pair(v0, v1, hw, lw);
            Oh[(long)R0 * 256 + (N0 >> 1)] = hw;
            Ol[(long)R0 * 256 + (N0 >> 1)] = lw;
            split_pair(v2, v3, hw, lw);
            Oh[(long)R1 * 256 + (N0 >> 1)] = hw;
            Ol[(long)R1 * 256 + (N0 >> 1)] = lw;
        }
    }
}

// FC1: gelu -> split H planes (z = e)
__global__ __launch_bounds__(256) void fc1_packed_kernel(
    const uint32_t* __restrict__ Ahp, const uint32_t* __restrict__ Alp,
    const uint32_t* __restrict__ Wh, const uint32_t* __restrict__ Wl,
    const float* __restrict__ fc1b,
    uint32_t* __restrict__ Hh, uint32_t* __restrict__ Hl)
{
    int e = blockIdx.z;
    const float* bias = fc1b + e * C_;
    int m0 = blockIdx.y * 128, n0 = blockIdx.x * 128;
    float4 acc[2][8];
    packed_main(Ahp + (long)e * TPE, Alp + (long)e * TPE,
                Wh + (long)(18 + e) * 131072, Wl + (long)(18 + e) * 131072, m0, n0, acc);

    uint32_t* Oh = Hh + (long)e * TPE;
    uint32_t* Ol = Hl + (long)e * TPE;
    int lane = threadIdx.x & 31, warp = threadIdx.x >> 5;
    int wm = warp & 3, wn = warp >> 2, g = lane >> 2, t = lane & 3;
#pragma unroll
    for (int mt = 0; mt < 2; mt++) {
        int R0 = m0 + wm * 32 + mt * 16 + g;
        int R1 = R0 + 8;
#pragma unroll
        for (int nt = 0; nt < 8; nt++) {
            int N0 = n0 + wn * 64 + nt * 8 + 2 * t;
            float b0 = bias[N0], b1 = bias[N0 + 1];
            float4 a = acc[mt][nt];
            float v0 = gelu_exact(a.x + b0), v1 = gelu_exact(a.y + b1);
            float v2 = gelu_exact(a.z + b0), v3 = gelu_exact(a.w + b1);
            uint32_t hw, lw;
            split_pair(v0, v1, hw, lw);
            Oh[(long)R0 * 256 + (N0 >> 1)] = hw;
            Ol[(long)R0 * 256 + (N0 >> 1)] = lw;
            split_pair(v2, v3, hw, lw);
            Oh[(long)R1 * 256 + (N0 >> 1)] = hw;
            Ol[(long)R1 * 256 + (N0 >> 1)] = lw;
        }
    }
}

// FC2: acc + bias + residual(XO fp32) -> stacked fp32 [m][e*C+n]
__global__ __launch_bounds__(256) void fc2_packed_kernel(
    const uint32_t* __restrict__ Hh, const uint32_t* __restrict__ Hl,
    const uint32_t* __restrict__ Wh, const uint32_t* __restrict__ Wl,
    const float* __restrict__ fc2b, const float* __restrict__ xo,
    float* __restrict__ stacked)
{
    int e = blockIdx.z;
    const float* bias = fc2b + e * C_;
    const float* res = xo + (long)e * M_ * C_;
    float* out = stacked + e * C_;
    int m0 = blockIdx.y * 128, n0 = blockIdx.x * 128;
    float4 acc[2][8];
    packed_main(Hh + (long)e * TPE, Hl + (long)e * TPE,
                Wh + (long)(24 + e) * 131072, Wl + (long)(24 + e) * 131072, m0, n0, acc);

    int lane = threadIdx.x & 31, warp = threadIdx.x >> 5;
    int wm = warp & 3, wn = warp >> 2, g = lane >> 2, t = lane & 3;
#pragma unroll
    for (int mt = 0; mt < 2; mt++) {
        int R0 = m0 + wm * 32 + mt * 16 + g;
        int R1 = R0 + 8;
#pragma unroll
        for (int nt = 0; nt < 8; nt++) {
            int N0 = n0 + wn * 64 + nt * 8 + 2 * t;
            float b0 = bias[N0], b1 = bias[N0 + 1];
            float4 a = acc[mt][nt];
            float2 r0 = *(const float2*)(res + (long)R0 * 512 + N0);
            float2 r1 = *(const float2*)(res + (long)R1 * 512 + N0);
            *(float2*)(out + (long)R0 * (E_ * C_) + N0) =
                make_float2(a.x + b0 + r0.x, a.y + b1 + r0.y);
            *(float2*)(out + (long)R1 * (E_ * C_) + N0) =
                make_float2(a.z + b0 + r1.x, a.w + b1 + r1.y);
        }
    }
}

// ---------------------------------------------------------------------------
// tf32x3 GEMM (router rh path)
// ---------------------------------------------------------------------------
#define RAW 2560
#define RBW 2176
#define RSMEM ((2*RAW + 2*RBW) * 2 * 4)

__global__ __launch_bounds__(256) void gemm_tf32x3_kernel(
    const float* __restrict__ A, const float* __restrict__ W,
    const float* __restrict__ bias, float* __restrict__ out)
{
    int m0 = blockIdx.y * 128;
    int n0 = blockIdx.x * 128;

    extern __shared__ uint32_t rs[];
    uint32_t* Ah = rs;
    uint32_t* Al = Ah + 2 * RAW;
    uint32_t* Bh = Al + 2 * RAW;
    uint32_t* Bl = Bh + 2 * RBW;

    int tid = threadIdx.x, lane = tid & 31, warp = tid >> 5;
    int wm = warp & 3, wn = warp >> 2, g = lane >> 2, t = lane & 3;

    int ar = tid >> 2;
    int ak = (tid & 3) << 2;
    const float* aptr = A + (long)(m0 + ar) * 512 + ak;
    int bk = tid >> 5;
    int bn = (tid & 31) << 2;
    const float* bptr = W + (long)bk * 512 + n0 + bn;

    int as0 = ar * 20 + ak, as1 = (ar + 64) * 20 + ak;
    int bs0 = bk * 136 + bn, bs1 = (bk + 8) * 136 + bn;

    float4 acc[2][8];
#pragma unroll
    for (int i = 0; i < 2; i++)
#pragma unroll
        for (int j = 0; j < 8; j++) acc[i][j] = make_float4(0.f, 0.f, 0.f, 0.f);

    auto st = [&](int buf, float4 a0v, float4 a1v, float4 b0v, float4 b1v) {
        uint32_t* ah = Ah + buf * RAW;  uint32_t* al = Al + buf * RAW;
        uint32_t* bh = Bh + buf * RBW;  uint32_t* bl = Bl + buf * RBW;
        uint32_t h, l;
        tf32_split(a0v.x, h, l); ah[as0+0]=h; al[as0+0]=l;
        tf32_split(a0v.y, h, l); ah[as0+1]=h; al[as0+1]=l;
        tf32_split(a0v.z, h, l); ah[as0+2]=h; al[as0+2]=l;
        tf32_split(a0v.w, h, l); ah[as0+3]=h; al[as0+3]=l;
        tf32_split(a1v.x, h, l); ah[as1+0]=h; al[as1+0]=l;
        tf32_split(a1v.y, h, l); ah[as1+1]=h; al[as1+1]=l;
        tf32_split(a1v.z, h, l); ah[as1+2]=h; al[as1+2]=l;
        tf32_split(a1v.w, h, l); ah[as1+3]=h; al[as1+3]=l;
        tf32_split(b0v.x, h, l); bh[bs0+0]=h; bl[bs0+0]=l;
        tf32_split(b0v.y, h, l); bh[bs0+1]=h; bl[bs0+1]=l;
        tf32_split(b0v.z, h, l); bh[bs0+2]=h; bl[bs0+2]=l;
        tf32_split(b0v.w, h, l); bh[bs0+3]=h; bl[bs0+3]=l;
        tf32_split(b1v.x, h, l); bh[bs1+0]=h; bl[bs1+0]=l;
        tf32_split(b1v.y, h, l); bh[bs1+1]=h; bl[bs1+1]=l;
        tf32_split(b1v.z, h, l); bh[bs1+2]=h; bl[bs1+2]=l;
        tf32_split(b1v.w, h, l); bh[bs1+3]=h; bl[bs1+3]=l;
    };

    {
        float4 a0v = *(const float4*)(aptr);
        float4 a1v = *(const float4*)(aptr + 64 * 512);
        float4 b0v = *(const float4*)(bptr);
        float4 b1v = *(const float4*)(bptr + 8 * 512);
        st(0, a0v, a1v, b0v, b1v);
    }
    __syncthreads();

    float4 pa0, pa1, pb0, pb1;
    for (int kt = 0; kt < 32; kt++) {
        int cur = kt & 1;
        if (kt + 1 < 32) {
            const float* ap = aptr + (kt + 1) * 16;
            const float* bp = bptr + (long)(kt + 1) * 16 * 512;
            pa0 = *(const float4*)(ap);
            pa1 = *(const float4*)(ap + 64 * 512);
            pb0 = *(const float4*)(bp);
            pb1 = *(const float4*)(bp + 8 * 512);
        }

        const uint32_t* ah = Ah + cur * RAW;
        const uint32_t* al = Al + cur * RAW;
        const uint32_t* bh = Bh + cur * RBW;
        const uint32_t* bl = Bl + cur * RBW;

#pragma unroll
        for (int k8 = 0; k8 < 16; k8 += 8) {
            uint32_t afh[2][4], afl[2][4];
#pragma unroll
            for (int mt = 0; mt < 2; mt++) {
                int row = wm * 32 + mt * 16 + g;
                int base = row * 20 + k8 + t;
                afh[mt][0] = ah[base];
                afh[mt][1] = ah[base + 8 * 20];
                afh[mt][2] = ah[base + 4];
                afh[mt][3] = ah[base + 8 * 20 + 4];
                afl[mt][0] = al[base];
                afl[mt][1] = al[base + 8 * 20];
                afl[mt][2] = al[base + 4];
                afl[mt][3] = al[base + 8 * 20 + 4];
            }
#pragma unroll
            for (int nt = 0; nt < 8; nt++) {
                int col = wn * 64 + nt * 8 + g;
                uint32_t bh0 = bh[(k8 + t) * 136 + col];
                uint32_t bh1 = bh[(k8 + 4 + t) * 136 + col];
                uint32_t bl0 = bl[(k8 + t) * 136 + col];
                uint32_t bl1 = bl[(k8 + 4 + t) * 136 + col];
#pragma unroll
                for (int mt = 0; mt < 2; mt++) {
                    mma_tf32(acc[mt][nt], afh[mt][0], afh[mt][1], afh[mt][2], afh[mt][3], bh0, bh1);
                    mma_tf32(acc[mt][nt], afh[mt][0], afh[mt][1], afh[mt][2], afh[mt][3], bl0, bl1);
                    mma_tf32(acc[mt][nt], afl[mt][0], afl[mt][1], afl[mt][2], afl[mt][3], bh0, bh1);
                }
            }
        }

        if (kt + 1 < 32) {
            st(cur ^ 1, pa0, pa1, pb0, pb1);
            __syncthreads();
        }
    }

#pragma unroll
    for (int mt = 0; mt < 2; mt++) {
        int R0 = m0 + wm * 32 + mt * 16 + g;
        int R1 = R0 + 8;
#pragma unroll
        for (int nt = 0; nt < 8; nt++) {
            int N0 = n0 + wn * 64 + nt * 8 + 2 * t;
            float b0 = bias[N0], b1 = bias[N0 + 1];
            float4 a = acc[mt][nt];
            *(float2*)(out + (long)R0 * 512 + N0) =
                make_float2(gelu_exact(a.x + b0), gelu_exact(a.y + b1));
            *(float2*)(out + (long)R1 * 512 + N0) =
                make_float2(gelu_exact(a.z + b0), gelu_exact(a.w + b1));
        }
    }
}

// ---------------------------------------------------------------------------
// MMA flash attention, packed-plane inputs.
// ---------------------------------------------------------------------------
#define KP36 36
#define VP35 35
#define PSP  68
#define ATT_SMEM (22912 * 4)

__global__ __launch_bounds__(256) void attn_mma_kernel(
    const uint32_t* __restrict__ Qph_g, const uint32_t* __restrict__ Qpl_g,
    const uint32_t* __restrict__ Kph_g, const uint32_t* __restrict__ Kpl_g,
    const uint32_t* __restrict__ Vph_g, const uint32_t* __restrict__ Vpl_g,
    const int* __restrict__ mask,
    float* __restrict__ XO,
    uint32_t* __restrict__ XOh_g, uint32_t* __restrict__ XOl_g)
{
    extern __shared__ uint32_t smu[];
    uint32_t* Qh = smu;
    uint32_t* Ql = Qh + 64 * KP36;
    uint32_t* Kh = Ql + 64 * KP36;
    uint32_t* Kl = Kh + 64 * KP36;
    uint32_t* Ph = Kl + 64 * KP36;
    uint32_t* Pl = Ph + 64 * KP36;
    uint32_t* Vh = Pl + 64 * KP36;
    uint32_t* Vl = Vh + 64 * VP35;
    float* Ps    = (float*)(Vl + 64 * VP35);
    float* rowm  = Ps + 64 * PSP;
    float* rowl  = rowm + 64;
    float* rowsc = rowl + 64;
    int*   ms    = (int*)(rowsc + 64);

    int tid = threadIdx.x;
    int lane = tid & 31, warp = tid >> 5;
    int wm = warp & 3, wn = warp >> 2;
    int g = lane >> 2, t = lane & 3;

    int h  = blockIdx.y;
    int eb = blockIdx.z;
    int b  = eb & (B_ - 1);
    int q0 = blockIdx.x * 64;

    const uint32_t* Qph = Qph_g + (long)eb * S_ * 256 + h * 32;
    const uint32_t* Qpl = Qpl_g + (long)eb * S_ * 256 + h * 32;
    const uint32_t* Kph = Kph_g + (long)eb * S_ * 256 + h * 32;
    const uint32_t* Kpl = Kpl_g + (long)eb * S_ * 256 + h * 32;
    const uint32_t* Vph = Vph_g + (long)eb * S_ * 256 + h * 32;
    const uint32_t* Vpl = Vpl_g + (long)eb * S_ * 256 + h * 32;
    float*    Op  = XO    + (long)eb * S_ * C_ + h * 64;
    uint32_t* Oph = XOh_g + (long)eb * S_ * 256 + h * 32;
    uint32_t* Opl = XOl_g + (long)eb * S_ * 256 + h * 32;
    const int* mrow = mask + b * 3 * S_;

    // Load Q (packed words, no conversion)
#pragma unroll
    for (int it = 0; it < 4; it++) {
        int lin = tid + it * 256;
        int r   = lin >> 4;
        int c2  = (lin & 15) << 1;   // word offset 0,2,...,30
        uint2 wh = *(const uint2*)(Qph + (long)(q0 + r) * 256 + c2);
        uint2 wl = *(const uint2*)(Qpl + (long)(q0 + r) * 256 + c2);
        Qh[r * KP36 + c2] = wh.x; Qh[r * KP36 + c2 + 1] = wh.y;
        Ql[r * KP36 + c2] = wl.x; Ql[r * KP36 + c2 + 1] = wl.y;
    }
    if (tid < 64) { rowm[tid] = -1e30f; rowl[tid] = 0.f; }

    int m0r = wm * 16 + g;
    int m1r = m0r + 8;

    float4 ofr[4];
#pragma unroll
    for (int nt = 0; nt < 4; nt++) ofr[nt] = make_float4(0.f, 0.f, 0.f, 0.f);

    for (int t0 = 0; t0 < S_; t0 += 64) {
        __syncthreads();
        // Load K + V (packed); transpose V via shfl
#pragma unroll
        for (int it = 0; it < 4; it++) {
            int lin = tid + it * 256;
            int r   = lin >> 4;
            int c2  = (lin & 15) << 1;
            uint2 kh = *(const uint2*)(Kph + (long)(t0 + r) * 256 + c2);
            uint2 kl = *(const uint2*)(Kpl + (long)(t0 + r) * 256 + c2);
            Kh[r * KP36 + c2] = kh.x; Kh[r * KP36 + c2 + 1] = kh.y;
            Kl[r * KP36 + c2] = kl.x; Kl[r * KP36 + c2 + 1] = kl.y;

            uint2 vh = *(const uint2*)(Vph + (long)(t0 + r) * 256 + c2);
            uint2 vl = *(const uint2*)(Vpl + (long)(t0 + r) * 256 + c2);
            uint32_t H01 = vh.x, H23 = vh.y, L01 = vl.x, L23 = vl.y;
            uint32_t pH01 = __shfl_xor_sync(0xffffffffu, H01, 16);
            uint32_t pH23 = __shfl_xor_sync(0xffffffffu, H23, 16);
            uint32_t pL01 = __shfl_xor_sync(0xffffffffu, L01, 16);
            uint32_t pL23 = __shfl_xor_sync(0xffffffffu, L23, 16);
            int c4 = c2 << 1;     // d base
            int jp = r >> 1;
            if (lane < 16) {  // even j
                Vh[(c4 + 0) * VP35 + jp] = (H01 & 0xFFFFu) | (pH01 << 16);
                Vh[(c4 + 1) * VP35 + jp] = (H01 >> 16)     | (pH01 & 0xFFFF0000u);
                Vl[(c4 + 0) * VP35 + jp] = (L01 & 0xFFFFu) | (pL01 << 16);
                Vl[(c4 + 1) * VP35 + jp] = (L01 >> 16)     | (pL01 & 0xFFFF0000u);
            } else {          // odd j
                Vh[(c4 + 2) * VP35 + jp] = (pH23 & 0xFFFFu) | (H23 << 16);
                Vh[(c4 + 3) * VP35 + jp] = (pH23 >> 16)     | (H23 & 0xFFFF0000u);
                Vl[(c4 + 2) * VP35 + jp] = (pL23 & 0xFFFFu) | (L23 << 16);
                Vl[(c4 + 3) * VP35 + jp] = (pL23 >> 16)     | (L23 & 0xFFFF0000u);
            }
        }
        if (tid < 64) ms[tid] = mrow[t0 + tid];
        __syncthreads();

        // S = Q @ K^T (bf16x3)
        float4 sfr[4];
#pragma unroll
        for (int nt = 0; nt < 4; nt++) sfr[nt] = make_float4(0.f, 0.f, 0.f, 0.f);
#pragma unroll
        for (int kk = 0; kk < 4; kk++) {
            int a0 = m0r * KP36 + kk * 8 + t;
            int a1 = m1r * KP36 + kk * 8 + t;
            uint32_t ah0 = Qh[a0], ah1 = Qh[a1], ah2 = Qh[a0 + 4], ah3 = Qh[a1 + 4];
            uint32_t al0 = Ql[a0], al1 = Ql[a1], al2 = Ql[a0 + 4], al3 = Ql[a1 + 4];
#pragma unroll
            for (int nt = 0; nt < 4; nt++) {
                int j  = wn * 32 + nt * 8 + g;
                int bo = j * KP36 + kk * 8 + t;
                uint32_t bh0 = Kh[bo], bh1 = Kh[bo + 4];
                uint32_t bl0 = Kl[bo], bl1 = Kl[bo + 4];
                mma_bf16(sfr[nt], ah0, ah1, ah2, ah3, bh0, bh1);
                mma_bf16(sfr[nt], ah0, ah1, ah2, ah3, bl0, bl1);
                mma_bf16(sfr[nt], al0, al1, al2, al3, bh0, bh1);
            }
        }
#pragma unroll
        for (int nt = 0; nt < 4; nt++) {
            int c0 = wn * 32 + nt * 8 + 2 * t;
            bool ok0 = ms[c0] != 0, ok1 = ms[c0 + 1] != 0;
            Ps[m0r * PSP + c0]     = ok0 ? sfr[nt].x : -1e30f;
            Ps[m0r * PSP + c0 + 1] = ok1 ? sfr[nt].y : -1e30f;
            Ps[m1r * PSP + c0]     = ok0 ? sfr[nt].z : -1e30f;
            Ps[m1r * PSP + c0 + 1] = ok1 ? sfr[nt].w : -1e30f;
        }
        __syncthreads();

        // Online softmax; P -> split bf16 [q][jpair]
        {
            int row = tid >> 2, quad = tid & 3;
            float p[16];
            const float* pr = &Ps[row * PSP + quad * 16];
            float mx = -1e30f;
#pragma unroll
            for (int t4 = 0; t4 < 4; t4++) {
                float4 v = *(const float4*)(pr + t4 * 4);
                p[t4*4+0] = v.x; p[t4*4+1] = v.y; p[t4*4+2] = v.z; p[t4*4+3] = v.w;
                mx = fmaxf(mx, fmaxf(fmaxf(v.x, v.y), fmaxf(v.z, v.w)));
            }
            mx = fmaxf(mx, __shfl_xor_sync(0xffffffffu, mx, 1));
            mx = fmaxf(mx, __shfl_xor_sync(0xffffffffu, mx, 2));
            float oldm = rowm[row];
            float newm = fmaxf(oldm, mx);
            float sum = 0.f;
#pragma unroll
            for (int tt = 0; tt < 16; tt++) {
                float e = __expf(p[tt] - newm);
                p[tt] = e;
                sum += e;
            }
            sum += __shfl_xor_sync(0xffffffffu, sum, 1);
            sum += __shfl_xor_sync(0xffffffffu, sum, 2);
            float scale = __expf(oldm - newm);
            __nv_bfloat16* phb = (__nv_bfloat16*)Ph;
            __nv_bfloat16* plb = (__nv_bfloat16*)Pl;
#pragma unroll
            for (int tt = 0; tt < 16; tt++) {
                int j = quad * 16 + tt;
                float f = p[tt];
                __nv_bfloat16 bh = __float2bfloat16_rn(f);
                float rl = f - __bfloat162float(bh);
                phb[row * (2 * KP36) + j] = bh;
                plb[row * (2 * KP36) + j] = __float2bfloat16_rn(rl);
            }
            if (quad == 0) {
                rowl[row] = rowl[row] * scale + sum;
                rowm[row] = newm;
                rowsc[row] = scale;
            }
        }
        __syncthreads();

        // O = O*scale + P @ V (bf16x3)
        float sc0 = rowsc[m0r], sc1 = rowsc[m1r];
#pragma unroll
        for (int nt = 0; nt < 4; nt++) {
            ofr[nt].x *= sc0; ofr[nt].y *= sc0;
            ofr[nt].z *= sc1; ofr[nt].w *= sc1;
        }
#pragma unroll
        for (int kk = 0; kk < 4; kk++) {
            int a0 = m0r * KP36 + kk * 8 + t;
            int a1 = m1r * KP36 + kk * 8 + t;
            uint32_t ah0 = Ph[a0], ah1 = Ph[a1], ah2 = Ph[a0 + 4], ah3 = Ph[a1 + 4];
            uint32_t al0 = Pl[a0], al1 = Pl[a1], al2 = Pl[a0 + 4], al3 = Pl[a1 + 4];
#pragma unroll
            for (int nt = 0; nt < 4; nt++) {
                int d  = wn * 32 + nt * 8 + g;
                int bo = d * VP35 + kk * 8 + t;
                uint32_t bh0 = Vh[bo], bh1 = Vh[bo + 4];
                uint32_t bl0 = Vl[bo], bl1 = Vl[bo + 4];
                mma_bf16(ofr[nt], ah0, ah1, ah2, ah3, bh0, bh1);
                mma_bf16(ofr[nt], ah0, ah1, ah2, ah3, bl0, bl1);
                mma_bf16(ofr[nt], al0, al1, al2, al3, bh0, bh1);
            }
        }
    }

    // Final normalize + write fp32 XO and split planes
    float l0 = rowl[m0r], l1 = rowl[m1r];
    float inv0 = (l0 > 0.f) ? (1.f / l0) : 0.f;
    float inv1 = (l1 > 0.f) ? (1.f / l1) : 0.f;
#pragma unroll
    for (int nt = 0; nt < 4; nt++) {
        int c0 = wn * 32 + nt * 8 + 2 * t;
        float o00 = ofr[nt].x * inv0, o01 = ofr[nt].y * inv0;
        float o10 = ofr[nt].z * inv1, o11 = ofr[nt].w * inv1;
        *(float2*)(Op + (long)(q0 + m0r) * C_ + c0) = make_float2(o00, o01);
        *(float2*)(Op + (long)(q0 + m1r) * C_ + c0) = make_float2(o10, o11);
        uint32_t hw, lw;
        split_pair(o00, o01, hw, lw);
        Oph[(long)(q0 + m0r) * 256 + (c0 >> 1)] = hw;
        Opl[(long)(q0 + m0r) * 256 + (c0 >> 1)] = lw;
        split_pair(o10, o11, hw, lw);
        Oph[(long)(q0 + m1r) * 256 + (c0 >> 1)] = hw;
        Opl[(long)(q0 + m1r) * 256 + (c0 >> 1)] = lw;
    }
}

// ---------------------------------------------------------------------------
// Router + aggregation
// ---------------------------------------------------------------------------
__global__ __launch_bounds__(256) void router_kernel(
    const float* __restrict__ rh, const float* __restrict__ rw2,
    const float* __restrict__ rb2, float* __restrict__ sparse)
{
    int gwarp = (blockIdx.x * blockDim.x + threadIdx.x) >> 5;
    int lane  = threadIdx.x & 31;
    if (gwarp >= M_) return;

    const float* r = rh + (long)gwarp * RH_;
    float acc[E_];
#pragma unroll
    for (int e = 0; e < E_; e++) acc[e] = 0.f;
    for (int hh = lane; hh < RH_; hh += 32) {
        float xv = r[hh];
        const float* w = rw2 + hh * E_;
#pragma unroll
        for (int e = 0; e < E_; e++) acc[e] += xv * w[e];
    }
#pragma unroll
    for (int off = 16; off > 0; off >>= 1)
#pragma unroll
        for (int e = 0; e < E_; e++)
            acc[e] += __shfl_xor_sync(0xffffffffu, acc[e], off);

    if (lane == 0) {
        float lg[E_];
        float mx = -1e30f;
#pragma unroll
        for (int e = 0; e < E_; e++) { lg[e] = acc[e] + rb2[e]; mx = fmaxf(mx, lg[e]); }
        float sum = 0.f;
#pragma unroll
        for (int e = 0; e < E_; e++) { lg[e] = __expf(lg[e] - mx); sum += lg[e]; }
        float inv = 1.f / sum;
#pragma unroll
        for (int e = 0; e < E_; e++) lg[e] *= inv;
        int i1 = 0;
#pragma unroll
        for (int e = 1; e < E_; e++) if (lg[e] > lg[i1]) i1 = e;
        int i2 = (i1 == 0) ? 1 : 0;
#pragma unroll
        for (int e = 0; e < E_; e++) if (e != i1 && lg[e] > lg[i2]) i2 = e;
        float denom = fmaxf(lg[i1] + lg[i2], EPS_);
        float outv[E_];
#pragma unroll
        for (int e = 0; e < E_; e++) outv[e] = 0.f;
        outv[i1] = lg[i1] / denom;
        outv[i2] = lg[i2] / denom;
        float* o = sparse + (long)gwarp * E_;
#pragma unroll
        for (int e = 0; e < E_; e++) o[e] = outv[e];
    }
}

__global__ __launch_bounds__(256) void agg_kernel(
    const float* __restrict__ stacked, const float* __restrict__ sparse,
    float* __restrict__ agg)
{
    int idx = blockIdx.x * blockDim.x + threadIdx.x;
    if (idx >= M_ * (C_ / 4)) return;
    int m  = idx >> 7;
    int c  = (idx & 127) << 2;
    const float* sp = sparse + (long)m * E_;
    float w[E_];
#pragma unroll
    for (int e = 0; e < E_; e++) w[e] = sp[e];
    float4 a = {0.f, 0.f, 0.f, 0.f};
#pragma unroll
    for (int e = 0; e < E_; e++) {
        float4 v = *(const float4*)(stacked + ((long)m * E_ + e) * C_ + c);
        a.x += w[e] * v.x; a.y += w[e] * v.y; a.z += w[e] * v.z; a.w += w[e] * v.w;
    }
    *(float4*)(agg + (long)m * C_ + c) = a;
}

// ---------------------------------------------------------------------------
// Launch
// ---------------------------------------------------------------------------
extern "C" void kernel_launch(void* const* d_in, const int* in_sizes, int n_in,
                              void* d_out, int out_size)
{
    const float* x    = (const float*)d_in[0];
    const int*   mask = (const int*)d_in[1];
    const float* qw   = (const float*)d_in[2];
    const float* qb   = (const float*)d_in[3];
    const float* kw   = (const float*)d_in[4];
    const float* kb   = (const float*)d_in[5];
    const float* vw   = (const float*)d_in[6];
    const float* vb   = (const float*)d_in[7];
    const float* fc1w = (const float*)d_in[8];
    const float* fc1b = (const float*)d_in[9];
    const float* fc2w = (const float*)d_in[10];
    const float* fc2b = (const float*)d_in[11];
    const float* rw1  = (const float*)d_in[12];
    const float* rb1  = (const float*)d_in[13];
    const float* rw2  = (const float*)d_in[14];
    const float* rb2  = (const float*)d_in[15];

    float* out     = (float*)d_out;
    float* agg     = out;
    float* stacked = out + STACK_OFF;
    float* sparse  = out + SPARSE_OFF;

    uint32_t *xh, *xl, *wph, *wpl;
    uint32_t *qph, *qpl, *kph, *kpl, *vph, *vpl, *xoph, *xopl, *hph, *hpl;
    float *gxo, *grh;
    cudaGetSymbolAddress((void**)&xh,   g_Xh);
    cudaGetSymbolAddress((void**)&xl,   g_Xl);
    cudaGetSymbolAddress((void**)&wph,  g_Wph);
    cudaGetSymbolAddress((void**)&wpl,  g_Wpl);
    cudaGetSymbolAddress((void**)&qph,  g_Qph);
    cudaGetSymbolAddress((void**)&qpl,  g_Qpl);
    cudaGetSymbolAddress((void**)&kph,  g_Kph);
    cudaGetSymbolAddress((void**)&kpl,  g_Kpl);
    cudaGetSymbolAddress((void**)&vph,  g_Vph);
    cudaGetSymbolAddress((void**)&vpl,  g_Vpl);
    cudaGetSymbolAddress((void**)&xoph, g_XOph);
    cudaGetSymbolAddress((void**)&xopl, g_XOpl);
    cudaGetSymbolAddress((void**)&hph,  g_Hph);
    cudaGetSymbolAddress((void**)&hpl,  g_Hpl);
    cudaGetSymbolAddress((void**)&gxo,  g_XO);
    cudaGetSymbolAddress((void**)&grh,  g_RH);

    cudaFuncSetAttribute(qkv_packed_kernel, cudaFuncAttributeMaxDynamicSharedMemorySize, GSMEM);
    cudaFuncSetAttribute(fc1_packed_kernel, cudaFuncAttributeMaxDynamicSharedMemorySize, GSMEM);
    cudaFuncSetAttribute(fc2_packed_kernel, cudaFuncAttributeMaxDynamicSharedMemorySize, GSMEM);
    cudaFuncSetAttribute(gemm_tf32x3_kernel, cudaFuncAttributeMaxDynamicSharedMemorySize, RSMEM);
    cudaFuncSetAttribute(attn_mma_kernel,    cudaFuncAttributeMaxDynamicSharedMemorySize, ATT_SMEM);

    // Prep: split x and weights into packed bf16 planes
    split_x_kernel<<<XPW / 256, 256>>>(x, xh, xl);
    split_w_kernel<<<WPW / 256, 256>>>(qw, kw, vw, fc1w, fc2w, wph, wpl);

    // Fused QKV (z = set*6 + e)
    {
        dim3 gq(4, 32, 18);
        qkv_packed_kernel<<<gq, 256, GSMEM>>>(xh, xl, wph, wpl, qb, kb, vb,
                                              qph, qpl, kph, kpl, vph, vpl);
    }

    // Attention
    {
        dim3 ag(S_ / 64, H_, E_ * B_);
        attn_mma_kernel<<<ag, 256, ATT_SMEM>>>(qph, qpl, kph, kpl, vph, vpl,
                                               mask, gxo, xoph, xopl);
    }

    // FFN
    {
        dim3 gf(4, 32, 6);
        fc1_packed_kernel<<<gf, 256, GSMEM>>>(xoph, xopl, wph, wpl, fc1b, hph, hpl);
        fc2_packed_kernel<<<gf, 256, GSMEM>>>(hph, hpl, wph, wpl, fc2b, gxo, stacked);
    }

    // Router: tf32x3 rh, then top-2
    {
        dim3 gr(4, 32, 1);
        gemm_tf32x3_kernel<<<gr, 256, RSMEM>>>(x, rw1, rb1, grh);
        router_kernel<<<(M_ * 32 + 255) / 256, 256>>>(grh, rw2, rb2, sparse);
    }

    agg_kernel<<<(M_ * (C_ / 4) + 255) / 256, 256>>>(stacked, sparse, agg);
}

// round 15
// speedup vs baseline: 2.1871x; 1.0196x over previous
#include <cuda_runtime.h>
#include <cuda_bf16.h>
#include <math.h>
#include <stdint.h>

// Problem constants
#define B_ 8
#define S_ 512
#define C_ 512
#define H_ 8
#define D_ 64
#define E_ 6
#define M_ 4096          // B*S
#define RH_ 512
#define EPS_ 1e-8f

#define AGG_ELEMS   (M_*C_)
#define STACK_ELEMS (M_*E_*C_)
#define STACK_OFF   (AGG_ELEMS)
#define SPARSE_OFF  (AGG_ELEMS + STACK_ELEMS)

// Packed split-bf16 planes: word = (bf16 lo16 = elem0, bf16 hi16 = elem1)
#define XPW  (M_*256)            // x plane words
#define WPW  (30*256*512)        // 5 sets x 6 experts, [z][kp][n]
#define TPE  (M_*256)            // per-expert activation plane words
#define TPW  (E_*TPE)

__device__ uint32_t g_Xh[XPW],  g_Xl[XPW];
__device__ uint32_t g_Wph[WPW], g_Wpl[WPW];
__device__ uint32_t g_Qph[TPW], g_Qpl[TPW];
__device__ uint32_t g_Kph[TPW], g_Kpl[TPW];
__device__ uint32_t g_Vph[TPW], g_Vpl[TPW];
__device__ uint32_t g_XOph[TPW], g_XOpl[TPW];
__device__ uint32_t g_Hph[TPW], g_Hpl[TPW];
__device__ float g_XO[E_*M_*C_];
__device__ float g_RH[M_*RH_];

__device__ __forceinline__ float gelu_exact(float v) {
    return 0.5f * v * (1.0f + erff(v * 0.70710678118654752f));
}

__device__ __forceinline__ void bf16_split(float f, unsigned short& h, unsigned short& l) {
    __nv_bfloat16 bh = __float2bfloat16_rn(f);
    float r = f - __bfloat162float(bh);
    __nv_bfloat16 bl = __float2bfloat16_rn(r);
    h = __bfloat16_as_ushort(bh);
    l = __bfloat16_as_ushort(bl);
}

__device__ __forceinline__ uint32_t pack2(unsigned short lo16, unsigned short hi16) {
    return ((uint32_t)hi16 << 16) | (uint32_t)lo16;
}

__device__ __forceinline__ void split_pair(float v0, float v1, uint32_t& hw, uint32_t& lw) {
    unsigned short h0, l0, h1, l1;
    bf16_split(v0, h0, l0);
    bf16_split(v1, h1, l1);
    hw = pack2(h0, h1);
    lw = pack2(l0, l1);
}

__device__ __forceinline__ void mma_bf16(float4& d,
    uint32_t a0, uint32_t a1, uint32_t a2, uint32_t a3,
    uint32_t b0, uint32_t b1)
{
    asm volatile(
        "mma.sync.aligned.m16n8k16.row.col.f32.bf16.bf16.f32 "
        "{%0,%1,%2,%3}, {%4,%5,%6,%7}, {%8,%9}, {%0,%1,%2,%3};\n"
        : "+f"(d.x), "+f"(d.y), "+f"(d.z), "+f"(d.w)
        : "r"(a0), "r"(a1), "r"(a2), "r"(a3), "r"(b0), "r"(b1));
}

__device__ __forceinline__ uint32_t f2tf32(float v) {
    uint32_t r;
    asm("cvt.rna.tf32.f32 %0, %1;" : "=r"(r) : "f"(v));
    return r;
}

__device__ __forceinline__ void tf32_split(float f, uint32_t& h, uint32_t& l) {
    h = f2tf32(f);
    l = f2tf32(f - __uint_as_float(h));
}

__device__ __forceinline__ void mma_tf32(float4& d,
    uint32_t a0, uint32_t a1, uint32_t a2, uint32_t a3,
    uint32_t b0, uint32_t b1)
{
    asm volatile(
        "mma.sync.aligned.m16n8k8.row.col.f32.tf32.tf32.f32 "
        "{%0,%1,%2,%3}, {%4,%5,%6,%7}, {%8,%9}, {%0,%1,%2,%3};\n"
        : "+f"(d.x), "+f"(d.y), "+f"(d.z), "+f"(d.w)
        : "r"(a0), "r"(a1), "r"(a2), "r"(a3), "r"(b0), "r"(b1));
}

// ---------------------------------------------------------------------------
// Prep kernels: split fp32 -> packed bf16 hi/lo planes
// ---------------------------------------------------------------------------
__global__ __launch_bounds__(256) void split_x_kernel(
    const float* __restrict__ x, uint32_t* __restrict__ xh, uint32_t* __restrict__ xl)
{
    int idx = blockIdx.x * 256 + threadIdx.x;
    if (idx >= XPW) return;
    float2 v = *(const float2*)(x + 2 * (long)idx);
    uint32_t hw, lw;
    split_pair(v.x, v.y, hw, lw);
    xh[idx] = hw; xl[idx] = lw;
}

__global__ __launch_bounds__(256) void split_w_kernel(
    const float* __restrict__ qw, const float* __restrict__ kw,
    const float* __restrict__ vw, const float* __restrict__ fc1w,
    const float* __restrict__ fc2w,
    uint32_t* __restrict__ wh, uint32_t* __restrict__ wl)
{
    int idx = blockIdx.x * 256 + threadIdx.x;
    if (idx >= WPW) return;
    int z   = idx >> 17;          // 131072 words per matrix
    int rem = idx & 131071;
    int kp  = rem >> 9;
    int n   = rem & 511;
    int set = z / 6, e = z - set * 6;
    const float* base = set == 0 ? qw : set == 1 ? kw : set == 2 ? vw : set == 3 ? fc1w : fc2w;
    const float* src = base + (long)e * 262144 + (long)(2 * kp) * 512 + n;
    uint32_t hw, lw;
    split_pair(src[0], src[512], hw, lw);
    wh[idx] = hw; wl[idx] = lw;
}

// ---------------------------------------------------------------------------
// Packed bf16x3 GEMM mainloop: A-planes [m][kp] (lda 256w), B-planes [kp][n] (ldb 512w)
// Tile 128x128x32 (16 kpairs). 256 threads = 8 warps of 32x64.
// ---------------------------------------------------------------------------
#define GSMEM ((2*2560 + 2*2560 + 2*2176 + 2*2176) * 4)  // 75776 bytes

__device__ __forceinline__ void packed_main(
    const uint32_t* __restrict__ Ah, const uint32_t* __restrict__ Al,
    const uint32_t* __restrict__ Bh, const uint32_t* __restrict__ Bl,
    int m0, int n0, float4 (&acc)[2][8])
{
    extern __shared__ uint32_t smw[];
    uint32_t* sAh = smw;                 // [2][2560]  pitch 20
    uint32_t* sAl = sAh + 2 * 2560;
    uint32_t* sBh = sAl + 2 * 2560;      // [2][2176]  pitch 136
    uint32_t* sBl = sBh + 2 * 2176;

    int tid = threadIdx.x, lane = tid & 31, warp = tid >> 5;
    int wm = warp & 3, wn = warp >> 2, g = lane >> 2, t = lane & 3;

    int ar = tid >> 2, kq = (tid & 3) << 2;
    const uint32_t* aph = Ah + (long)(m0 + ar) * 256 + kq;
    const uint32_t* apl = Al + (long)(m0 + ar) * 256 + kq;
    int br = tid >> 5, nq = (tid & 31) << 2;
    const uint32_t* bph = Bh + (long)br * 512 + n0 + nq;
    const uint32_t* bpl = Bl + (long)br * 512 + n0 + nq;

    int as0 = ar * 20 + kq, as1 = (ar + 64) * 20 + kq;
    int bs0 = br * 136 + nq, bs1 = (br + 8) * 136 + nq;

#pragma unroll
    for (int i = 0; i < 2; i++)
#pragma unroll
        for (int j = 0; j < 8; j++) acc[i][j] = make_float4(0.f, 0.f, 0.f, 0.f);

    uint4 ah0, ah1, al0, al1, bh0u, bh1u, bl0u, bl1u;

    // preload tile 0
    ah0  = *(const uint4*)(aph);
    ah1  = *(const uint4*)(aph + 64 * 256);
    al0  = *(const uint4*)(apl);
    al1  = *(const uint4*)(apl + 64 * 256);
    bh0u = *(const uint4*)(bph);
    bh1u = *(const uint4*)(bph + 8 * 512);
    bl0u = *(const uint4*)(bpl);
    bl1u = *(const uint4*)(bpl + 8 * 512);
    *(uint4*)(sAh + as0) = ah0;  *(uint4*)(sAh + as1) = ah1;
    *(uint4*)(sAl + as0) = al0;  *(uint4*)(sAl + as1) = al1;
    *(uint4*)(sBh + bs0) = bh0u; *(uint4*)(sBh + bs1) = bh1u;
    *(uint4*)(sBl + bs0) = bl0u; *(uint4*)(sBl + bs1) = bl1u;
    __syncthreads();

    const int NT = 16;   // 512 / 32
    for (int kt = 0; kt < NT; kt++) {
        int cur = kt & 1;
        if (kt + 1 < NT) {
            int ko = (kt + 1) * 16;
            ah0  = *(const uint4*)(aph + ko);
            ah1  = *(const uint4*)(aph + 64 * 256 + ko);
            al0  = *(const uint4*)(apl + ko);
            al1  = *(const uint4*)(apl + 64 * 256 + ko);
            bh0u = *(const uint4*)(bph + (long)ko * 512);
            bh1u = *(const uint4*)(bph + (long)(ko + 8) * 512);
            bl0u = *(const uint4*)(bpl + (long)ko * 512);
            bl1u = *(const uint4*)(bpl + (long)(ko + 8) * 512);
        }

        const uint32_t* ah = sAh + cur * 2560;
        const uint32_t* al = sAl + cur * 2560;
        const uint32_t* bh = sBh + cur * 2176;
        const uint32_t* bl = sBl + cur * 2176;

#pragma unroll
        for (int kk = 0; kk < 2; kk++) {
            uint32_t afh[2][4], afl[2][4];
#pragma unroll
            for (int mt = 0; mt < 2; mt++) {
                int row = wm * 32 + mt * 16 + g;
                int base = row * 20 + kk * 8 + t;
                afh[mt][0] = ah[base];
                afh[mt][1] = ah[base + 8 * 20];
                afh[mt][2] = ah[base + 4];
                afh[mt][3] = ah[base + 8 * 20 + 4];
                afl[mt][0] = al[base];
                afl[mt][1] = al[base + 8 * 20];
                afl[mt][2] = al[base + 4];
                afl[mt][3] = al[base + 8 * 20 + 4];
            }
#pragma unroll
            for (int nt = 0; nt < 8; nt++) {
                int col = wn * 64 + nt * 8 + g;
                int bbase = (kk * 8 + t) * 136 + col;
                uint32_t bh0 = bh[bbase];
                uint32_t bh1 = bh[bbase + 4 * 136];
                uint32_t bl0 = bl[bbase];
                uint32_t bl1 = bl[bbase + 4 * 136];
#pragma unroll
                for (int mt = 0; mt < 2; mt++) {
                    mma_bf16(acc[mt][nt], afh[mt][0], afh[mt][1], afh[mt][2], afh[mt][3], bh0, bh1);
                    mma_bf16(acc[mt][nt], afh[mt][0], afh[mt][1], afh[mt][2], afh[mt][3], bl0, bl1);
                    mma_bf16(acc[mt][nt], afl[mt][0], afl[mt][1], afl[mt][2], afl[mt][3], bh0, bh1);
                }
            }
        }

        if (kt + 1 < NT) {
            int nxt = cur ^ 1;
            *(uint4*)(sAh + nxt * 2560 + as0) = ah0;
            *(uint4*)(sAh + nxt * 2560 + as1) = ah1;
            *(uint4*)(sAl + nxt * 2560 + as0) = al0;
            *(uint4*)(sAl + nxt * 2560 + as1) = al1;
            *(uint4*)(sBh + nxt * 2176 + bs0) = bh0u;
            *(uint4*)(sBh + nxt * 2176 + bs1) = bh1u;
            *(uint4*)(sBl + nxt * 2176 + bs0) = bl0u;
            *(uint4*)(sBl + nxt * 2176 + bs1) = bl1u;
            __syncthreads();
        }
    }
}

// Fused QKV: z = set*6 + e, set in {0:Q,1:K,2:V}
__global__ __launch_bounds__(256) void qkv_packed_kernel(
    const uint32_t* __restrict__ Xh, const uint32_t* __restrict__ Xl,
    const uint32_t* __restrict__ Wh, const uint32_t* __restrict__ Wl,
    const float* __restrict__ qb, const float* __restrict__ kb, const float* __restrict__ vb,
    uint32_t* __restrict__ Qh, uint32_t* __restrict__ Ql,
    uint32_t* __restrict__ Kh, uint32_t* __restrict__ Kl,
    uint32_t* __restrict__ Vh, uint32_t* __restrict__ Vl)
{
    int z = blockIdx.z;
    int set = z / 6, e = z - set * 6;
    const float* bias = (set == 0 ? qb : set == 1 ? kb : vb) + e * C_;
    float alpha = (set == 0) ? 0.125f : 1.0f;
    uint32_t* Oh = (set == 0 ? Qh : set == 1 ? Kh : Vh) + (long)e * TPE;
    uint32_t* Ol = (set == 0 ? Ql : set == 1 ? Kl : Vl) + (long)e * TPE;

    int m0 = blockIdx.y * 128, n0 = blockIdx.x * 128;
    float4 acc[2][8];
    packed_main(Xh, Xl, Wh + (long)z * 131072, Wl + (long)z * 131072, m0, n0, acc);

    int lane = threadIdx.x & 31, warp = threadIdx.x >> 5;
    int wm = warp & 3, wn = warp >> 2, g = lane >> 2, t = lane & 3;
#pragma unroll
    for (int mt = 0; mt < 2; mt++) {
        int R0 = m0 + wm * 32 + mt * 16 + g;
        int R1 = R0 + 8;
#pragma unroll
        for (int nt = 0; nt < 8; nt++) {
            int N0 = n0 + wn * 64 + nt * 8 + 2 * t;
            float b0 = bias[N0], b1 = bias[N0 + 1];
            float4 a = acc[mt][nt];
            float v0 = (a.x + b0) * alpha, v1 = (a.y + b1) * alpha;
            float v2 = (a.z + b0) * alpha, v3 = (a.w + b1) * alpha;
            uint32_t hw, lw;
            split_pair(v0, v1, hw, lw);
            Oh[(long)R0 * 256 + (N0 >> 1)] = hw;
            Ol[(long)R0 * 256 + (N0 >> 1)] = lw;
            split_pair(v2, v3, hw, lw);
            Oh[(long)R1 * 256 + (N0 >> 1)] = hw;
            Ol[(long)R1 * 256 + (N0 >> 1)] = lw;
        }
    }
}

// FC1: gelu -> split H planes (z = e)
__global__ __launch_bounds__(256) void fc1_packed_kernel(
    const uint32_t* __restrict__ Ahp, const uint32_t* __restrict__ Alp,
    const uint32_t* __restrict__ Wh, const uint32_t* __restrict__ Wl,
    const float* __restrict__ fc1b,
    uint32_t* __restrict__ Hh, uint32_t* __restrict__ Hl)
{
    int e = blockIdx.z;
    const float* bias = fc1b + e * C_;
    int m0 = blockIdx.y * 128, n0 = blockIdx.x * 128;
    float4 acc[2][8];
    packed_main(Ahp + (long)e * TPE, Alp + (long)e * TPE,
                Wh + (long)(18 + e) * 131072, Wl + (long)(18 + e) * 131072, m0, n0, acc);

    uint32_t* Oh = Hh + (long)e * TPE;
    uint32_t* Ol = Hl + (long)e * TPE;
    int lane = threadIdx.x & 31, warp = threadIdx.x >> 5;
    int wm = warp & 3, wn = warp >> 2, g = lane >> 2, t = lane & 3;
#pragma unroll
    for (int mt = 0; mt < 2; mt++) {
        int R0 = m0 + wm * 32 + mt * 16 + g;
        int R1 = R0 + 8;
#pragma unroll
        for (int nt = 0; nt < 8; nt++) {
            int N0 = n0 + wn * 64 + nt * 8 + 2 * t;
            float b0 = bias[N0], b1 = bias[N0 + 1];
            float4 a = acc[mt][nt];
            float v0 = gelu_exact(a.x + b0), v1 = gelu_exact(a.y + b1);
            float v2 = gelu_exact(a.z + b0), v3 = gelu_exact(a.w + b1);
            uint32_t hw, lw;
            split_pair(v0, v1, hw, lw);
            Oh[(long)R0 * 256 + (N0 >> 1)] = hw;
            Ol[(long)R0 * 256 + (N0 >> 1)] = lw;
            split_pair(v2, v3, hw, lw);
            Oh[(long)R1 * 256 + (N0 >> 1)] = hw;
            Ol[(long)R1 * 256 + (N0 >> 1)] = lw;
        }
    }
}

// FC2: acc + bias + residual(XO fp32) -> stacked fp32 [m][e*C+n]
__global__ __launch_bounds__(256) void fc2_packed_kernel(
    const uint32_t* __restrict__ Hh, const uint32_t* __restrict__ Hl,
    const uint32_t* __restrict__ Wh, const uint32_t* __restrict__ Wl,
    const float* __restrict__ fc2b, const float* __restrict__ xo,
    float* __restrict__ stacked)
{
    int e = blockIdx.z;
    const float* bias = fc2b + e * C_;
    const float* res = xo + (long)e * M_ * C_;
    float* out = stacked + e * C_;
    int m0 = blockIdx.y * 128, n0 = blockIdx.x * 128;
    float4 acc[2][8];
    packed_main(Hh + (long)e * TPE, Hl + (long)e * TPE,
                Wh + (long)(24 + e) * 131072, Wl + (long)(24 + e) * 131072, m0, n0, acc);

    int lane = threadIdx.x & 31, warp = threadIdx.x >> 5;
    int wm = warp & 3, wn = warp >> 2, g = lane >> 2, t = lane & 3;
#pragma unroll
    for (int mt = 0; mt < 2; mt++) {
        int R0 = m0 + wm * 32 + mt * 16 + g;
        int R1 = R0 + 8;
#pragma unroll
        for (int nt = 0; nt < 8; nt++) {
            int N0 = n0 + wn * 64 + nt * 8 + 2 * t;
            float b0 = bias[N0], b1 = bias[N0 + 1];
            float4 a = acc[mt][nt];
            float2 r0 = *(const float2*)(res + (long)R0 * 512 + N0);
            float2 r1 = *(const float2*)(res + (long)R1 * 512 + N0);
            *(float2*)(out + (long)R0 * (E_ * C_) + N0) =
                make_float2(a.x + b0 + r0.x, a.y + b1 + r0.y);
            *(float2*)(out + (long)R1 * (E_ * C_) + N0) =
                make_float2(a.z + b0 + r1.x, a.w + b1 + r1.y);
        }
    }
}

// ---------------------------------------------------------------------------
// tf32x3 GEMM (router rh path)
// ---------------------------------------------------------------------------
#define RAW 2560
#define RBW 2176
#define RSMEM ((2*RAW + 2*RBW) * 2 * 4)

__global__ __launch_bounds__(256) void gemm_tf32x3_kernel(
    const float* __restrict__ A, const float* __restrict__ W,
    const float* __restrict__ bias, float* __restrict__ out)
{
    int m0 = blockIdx.y * 128;
    int n0 = blockIdx.x * 128;

    extern __shared__ uint32_t rs[];
    uint32_t* Ah = rs;
    uint32_t* Al = Ah + 2 * RAW;
    uint32_t* Bh = Al + 2 * RAW;
    uint32_t* Bl = Bh + 2 * RBW;

    int tid = threadIdx.x, lane = tid & 31, warp = tid >> 5;
    int wm = warp & 3, wn = warp >> 2, g = lane >> 2, t = lane & 3;

    int ar = tid >> 2;
    int ak = (tid & 3) << 2;
    const float* aptr = A + (long)(m0 + ar) * 512 + ak;
    int bk = tid >> 5;
    int bn = (tid & 31) << 2;
    const float* bptr = W + (long)bk * 512 + n0 + bn;

    int as0 = ar * 20 + ak, as1 = (ar + 64) * 20 + ak;
    int bs0 = bk * 136 + bn, bs1 = (bk + 8) * 136 + bn;

    float4 acc[2][8];
#pragma unroll
    for (int i = 0; i < 2; i++)
#pragma unroll
        for (int j = 0; j < 8; j++) acc[i][j] = make_float4(0.f, 0.f, 0.f, 0.f);

    auto st = [&](int buf, float4 a0v, float4 a1v, float4 b0v, float4 b1v) {
        uint32_t* ah = Ah + buf * RAW;  uint32_t* al = Al + buf * RAW;
        uint32_t* bh = Bh + buf * RBW;  uint32_t* bl = Bl + buf * RBW;
        uint32_t h, l;
        tf32_split(a0v.x, h, l); ah[as0+0]=h; al[as0+0]=l;
        tf32_split(a0v.y, h, l); ah[as0+1]=h; al[as0+1]=l;
        tf32_split(a0v.z, h, l); ah[as0+2]=h; al[as0+2]=l;
        tf32_split(a0v.w, h, l); ah[as0+3]=h; al[as0+3]=l;
        tf32_split(a1v.x, h, l); ah[as1+0]=h; al[as1+0]=l;
        tf32_split(a1v.y, h, l); ah[as1+1]=h; al[as1+1]=l;
        tf32_split(a1v.z, h, l); ah[as1+2]=h; al[as1+2]=l;
        tf32_split(a1v.w, h, l); ah[as1+3]=h; al[as1+3]=l;
        tf32_split(b0v.x, h, l); bh[bs0+0]=h; bl[bs0+0]=l;
        tf32_split(b0v.y, h, l); bh[bs0+1]=h; bl[bs0+1]=l;
        tf32_split(b0v.z, h, l); bh[bs0+2]=h; bl[bs0+2]=l;
        tf32_split(b0v.w, h, l); bh[bs0+3]=h; bl[bs0+3]=l;
        tf32_split(b1v.x, h, l); bh[bs1+0]=h; bl[bs1+0]=l;
        tf32_split(b1v.y, h, l); bh[bs1+1]=h; bl[bs1+1]=l;
        tf32_split(b1v.z, h, l); bh[bs1+2]=h; bl[bs1+2]=l;
        tf32_split(b1v.w, h, l); bh[bs1+3]=h; bl[bs1+3]=l;
    };

    {
        float4 a0v = *(const float4*)(aptr);
        float4 a1v = *(const float4*)(aptr + 64 * 512);
        float4 b0v = *(const float4*)(bptr);
        float4 b1v = *(const float4*)(bptr + 8 * 512);
        st(0, a0v, a1v, b0v, b1v);
    }
    __syncthreads();

    float4 pa0, pa1, pb0, pb1;
    for (int kt = 0; kt < 32; kt++) {
        int cur = kt & 1;
        if (kt + 1 < 32) {
            const float* ap = aptr + (kt + 1) * 16;
            const float* bp = bptr + (long)(kt + 1) * 16 * 512;
            pa0 = *(const float4*)(ap);
            pa1 = *(const float4*)(ap + 64 * 512);
            pb0 = *(const float4*)(bp);
            pb1 = *(const float4*)(bp + 8 * 512);
        }

        const uint32_t* ah = Ah + cur * RAW;
        const uint32_t* al = Al + cur * RAW;
        const uint32_t* bh = Bh + cur * RBW;
        const uint32_t* bl = Bl + cur * RBW;

#pragma unroll
        for (int k8 = 0; k8 < 16; k8 += 8) {
            uint32_t afh[2][4], afl[2][4];
#pragma unroll
            for (int mt = 0; mt < 2; mt++) {
                int row = wm * 32 + mt * 16 + g;
                int base = row * 20 + k8 + t;
                afh[mt][0] = ah[base];
                afh[mt][1] = ah[base + 8 * 20];
                afh[mt][2] = ah[base + 4];
                afh[mt][3] = ah[base + 8 * 20 + 4];
                afl[mt][0] = al[base];
                afl[mt][1] = al[base + 8 * 20];
                afl[mt][2] = al[base + 4];
                afl[mt][3] = al[base + 8 * 20 + 4];
            }
#pragma unroll
            for (int nt = 0; nt < 8; nt++) {
                int col = wn * 64 + nt * 8 + g;
                uint32_t bh0 = bh[(k8 + t) * 136 + col];
                uint32_t bh1 = bh[(k8 + 4 + t) * 136 + col];
                uint32_t bl0 = bl[(k8 + t) * 136 + col];
                uint32_t bl1 = bl[(k8 + 4 + t) * 136 + col];
#pragma unroll
                for (int mt = 0; mt < 2; mt++) {
                    mma_tf32(acc[mt][nt], afh[mt][0], afh[mt][1], afh[mt][2], afh[mt][3], bh0, bh1);
                    mma_tf32(acc[mt][nt], afh[mt][0], afh[mt][1], afh[mt][2], afh[mt][3], bl0, bl1);
                    mma_tf32(acc[mt][nt], afl[mt][0], afl[mt][1], afl[mt][2], afl[mt][3], bh0, bh1);
                }
            }
        }

        if (kt + 1 < 32) {
            st(cur ^ 1, pa0, pa1, pb0, pb1);
            __syncthreads();
        }
    }

#pragma unroll
    for (int mt = 0; mt < 2; mt++) {
        int R0 = m0 + wm * 32 + mt * 16 + g;
        int R1 = R0 + 8;
#pragma unroll
        for (int nt = 0; nt < 8; nt++) {
            int N0 = n0 + wn * 64 + nt * 8 + 2 * t;
            float b0 = bias[N0], b1 = bias[N0 + 1];
            float4 a = acc[mt][nt];
            *(float2*)(out + (long)R0 * 512 + N0) =
                make_float2(gelu_exact(a.x + b0), gelu_exact(a.y + b1));
            *(float2*)(out + (long)R1 * 512 + N0) =
                make_float2(gelu_exact(a.z + b0), gelu_exact(a.w + b1));
        }
    }
}

// ---------------------------------------------------------------------------
// MMA flash attention, packed-plane inputs.
// P planes overlaid on fp32 S scratch: union row pitch 76 words.
// Row r: Ps fp32 words [r*76, r*76+64); P-hi words [r*76, r*76+38);
// P-lo words [r*76+38, r*76+76). Temporally disjoint per row (guarded by
// __syncwarp between Ps reads and P writes; only the owning warp touches a row).
// smem: Q/K (4*64*36) + V (2*64*35) + union (64*76) + stats = 18816 words.
// ---------------------------------------------------------------------------
#define KP36 36
#define VP35 35
#define PSP  76
#define ATT_SMEM (18816 * 4)   // 75264 bytes -> 3 blocks/SM

__global__ __launch_bounds__(256, 3) void attn_mma_kernel(
    const uint32_t* __restrict__ Qph_g, const uint32_t* __restrict__ Qpl_g,
    const uint32_t* __restrict__ Kph_g, const uint32_t* __restrict__ Kpl_g,
    const uint32_t* __restrict__ Vph_g, const uint32_t* __restrict__ Vpl_g,
    const int* __restrict__ mask,
    float* __restrict__ XO,
    uint32_t* __restrict__ XOh_g, uint32_t* __restrict__ XOl_g)
{
    extern __shared__ uint32_t smu[];
    uint32_t* Qh  = smu;
    uint32_t* Ql  = Qh + 64 * KP36;
    uint32_t* Kh  = Ql + 64 * KP36;
    uint32_t* Kl  = Kh + 64 * KP36;
    uint32_t* Vh  = Kl + 64 * KP36;
    uint32_t* Vl  = Vh + 64 * VP35;
    uint32_t* PsU = Vl + 64 * VP35;        // union: S fp32 / P split-bf16
    float* Ps    = (float*)PsU;
    float* rowm  = (float*)(PsU + 64 * PSP);
    float* rowl  = rowm + 64;
    float* rowsc = rowl + 64;
    int*   ms    = (int*)(rowsc + 64);

    int tid = threadIdx.x;
    int lane = tid & 31, warp = tid >> 5;
    int wm = warp & 3, wn = warp >> 2;
    int g = lane >> 2, t = lane & 3;

    int h  = blockIdx.y;
    int eb = blockIdx.z;
    int b  = eb & (B_ - 1);
    int q0 = blockIdx.x * 64;

    const uint32_t* Qph = Qph_g + (long)eb * S_ * 256 + h * 32;
    const uint32_t* Qpl = Qpl_g + (long)eb * S_ * 256 + h * 32;
    const uint32_t* Kph = Kph_g + (long)eb * S_ * 256 + h * 32;
    const uint32_t* Kpl = Kpl_g + (long)eb * S_ * 256 + h * 32;
    const uint32_t* Vph = Vph_g + (long)eb * S_ * 256 + h * 32;
    const uint32_t* Vpl = Vpl_g + (long)eb * S_ * 256 + h * 32;
    float*    Op  = XO    + (long)eb * S_ * C_ + h * 64;
    uint32_t* Oph = XOh_g + (long)eb * S_ * 256 + h * 32;
    uint32_t* Opl = XOl_g + (long)eb * S_ * 256 + h * 32;
    const int* mrow = mask + b * 3 * S_;

    // Load Q (packed words, no conversion)
#pragma unroll
    for (int it = 0; it < 4; it++) {
        int lin = tid + it * 256;
        int r   = lin >> 4;
        int c2  = (lin & 15) << 1;   // word offset 0,2,...,30
        uint2 wh = *(const uint2*)(Qph + (long)(q0 + r) * 256 + c2);
        uint2 wl = *(const uint2*)(Qpl + (long)(q0 + r) * 256 + c2);
        Qh[r * KP36 + c2] = wh.x; Qh[r * KP36 + c2 + 1] = wh.y;
        Ql[r * KP36 + c2] = wl.x; Ql[r * KP36 + c2 + 1] = wl.y;
    }
    if (tid < 64) { rowm[tid] = -1e30f; rowl[tid] = 0.f; }

    int m0r = wm * 16 + g;
    int m1r = m0r + 8;

    float4 ofr[4];
#pragma unroll
    for (int nt = 0; nt < 4; nt++) ofr[nt] = make_float4(0.f, 0.f, 0.f, 0.f);

    for (int t0 = 0; t0 < S_; t0 += 64) {
        __syncthreads();
        // Load K + V (packed); transpose V via shfl
#pragma unroll
        for (int it = 0; it < 4; it++) {
            int lin = tid + it * 256;
            int r   = lin >> 4;
            int c2  = (lin & 15) << 1;
            uint2 kh = *(const uint2*)(Kph + (long)(t0 + r) * 256 + c2);
            uint2 kl = *(const uint2*)(Kpl + (long)(t0 + r) * 256 + c2);
            Kh[r * KP36 + c2] = kh.x; Kh[r * KP36 + c2 + 1] = kh.y;
            Kl[r * KP36 + c2] = kl.x; Kl[r * KP36 + c2 + 1] = kl.y;

            uint2 vh = *(const uint2*)(Vph + (long)(t0 + r) * 256 + c2);
            uint2 vl = *(const uint2*)(Vpl + (long)(t0 + r) * 256 + c2);
            uint32_t H01 = vh.x, H23 = vh.y, L01 = vl.x, L23 = vl.y;
            uint32_t pH01 = __shfl_xor_sync(0xffffffffu, H01, 16);
            uint32_t pH23 = __shfl_xor_sync(0xffffffffu, H23, 16);
            uint32_t pL01 = __shfl_xor_sync(0xffffffffu, L01, 16);
            uint32_t pL23 = __shfl_xor_sync(0xffffffffu, L23, 16);
            int c4 = c2 << 1;     // d base
            int jp = r >> 1;
            if (lane < 16) {  // even j
                Vh[(c4 + 0) * VP35 + jp] = (H01 & 0xFFFFu) | (pH01 << 16);
                Vh[(c4 + 1) * VP35 + jp] = (H01 >> 16)     | (pH01 & 0xFFFF0000u);
                Vl[(c4 + 0) * VP35 + jp] = (L01 & 0xFFFFu) | (pL01 << 16);
                Vl[(c4 + 1) * VP35 + jp] = (L01 >> 16)     | (pL01 & 0xFFFF0000u);
            } else {          // odd j
                Vh[(c4 + 2) * VP35 + jp] = (pH23 & 0xFFFFu) | (H23 << 16);
                Vh[(c4 + 3) * VP35 + jp] = (pH23 >> 16)     | (H23 & 0xFFFF0000u);
                Vl[(c4 + 2) * VP35 + jp] = (pL23 & 0xFFFFu) | (L23 << 16);
                Vl[(c4 + 3) * VP35 + jp] = (pL23 >> 16)     | (L23 & 0xFFFF0000u);
            }
        }
        if (tid < 64) ms[tid] = mrow[t0 + tid];
        __syncthreads();

        // S = Q @ K^T (bf16x3)
        float4 sfr[4];
#pragma unroll
        for (int nt = 0; nt < 4; nt++) sfr[nt] = make_float4(0.f, 0.f, 0.f, 0.f);
#pragma unroll
        for (int kk = 0; kk < 4; kk++) {
            int a0 = m0r * KP36 + kk * 8 + t;
            int a1 = m1r * KP36 + kk * 8 + t;
            uint32_t ah0 = Qh[a0], ah1 = Qh[a1], ah2 = Qh[a0 + 4], ah3 = Qh[a1 + 4];
            uint32_t al0 = Ql[a0], al1 = Ql[a1], al2 = Ql[a0 + 4], al3 = Ql[a1 + 4];
#pragma unroll
            for (int nt = 0; nt < 4; nt++) {
                int j  = wn * 32 + nt * 8 + g;
                int bo = j * KP36 + kk * 8 + t;
                uint32_t bh0 = Kh[bo], bh1 = Kh[bo + 4];
                uint32_t bl0 = Kl[bo], bl1 = Kl[bo + 4];
                mma_bf16(sfr[nt], ah0, ah1, ah2, ah3, bh0, bh1);
                mma_bf16(sfr[nt], ah0, ah1, ah2, ah3, bl0, bl1);
                mma_bf16(sfr[nt], al0, al1, al2, al3, bh0, bh1);
            }
        }
#pragma unroll
        for (int nt = 0; nt < 4; nt++) {
            int c0 = wn * 32 + nt * 8 + 2 * t;
            bool ok0 = ms[c0] != 0, ok1 = ms[c0 + 1] != 0;
            Ps[m0r * PSP + c0]     = ok0 ? sfr[nt].x : -1e30f;
            Ps[m0r * PSP + c0 + 1] = ok1 ? sfr[nt].y : -1e30f;
            Ps[m1r * PSP + c0]     = ok0 ? sfr[nt].z : -1e30f;
            Ps[m1r * PSP + c0 + 1] = ok1 ? sfr[nt].w : -1e30f;
        }
        __syncthreads();

        // Online softmax; P written over Ps (union): hi at row*76, lo at +38
        {
            int row = tid >> 2, quad = tid & 3;
            float p[16];
            const float* pr = &Ps[row * PSP + quad * 16];
            float mx = -1e30f;
#pragma unroll
            for (int t4 = 0; t4 < 4; t4++) {
                float4 v = *(const float4*)(pr + t4 * 4);
                p[t4*4+0] = v.x; p[t4*4+1] = v.y; p[t4*4+2] = v.z; p[t4*4+3] = v.w;
                mx = fmaxf(mx, fmaxf(fmaxf(v.x, v.y), fmaxf(v.z, v.w)));
            }
            mx = fmaxf(mx, __shfl_xor_sync(0xffffffffu, mx, 1));
            mx = fmaxf(mx, __shfl_xor_sync(0xffffffffu, mx, 2));
            float oldm = rowm[row];
            float newm = fmaxf(oldm, mx);
            float sum = 0.f;
#pragma unroll
            for (int tt = 0; tt < 16; tt++) {
                float e = __expf(p[tt] - newm);
                p[tt] = e;
                sum += e;
            }
            sum += __shfl_xor_sync(0xffffffffu, sum, 1);
            sum += __shfl_xor_sync(0xffffffffu, sum, 2);
            float scale = __expf(oldm - newm);
            __syncwarp();   // all Ps reads of this warp's rows complete before overwrite
            __nv_bfloat16* pb = (__nv_bfloat16*)PsU;
#pragma unroll
            for (int tt = 0; tt < 16; tt++) {
                int j = quad * 16 + tt;
                float f = p[tt];
                __nv_bfloat16 bh = __float2bfloat16_rn(f);
                float rl = f - __bfloat162float(bh);
                pb[row * (2 * PSP) + j]            = bh;                       // hi
                pb[row * (2 * PSP) + 2 * 38 + j]   = __float2bfloat16_rn(rl);  // lo
            }
            if (quad == 0) {
                rowl[row] = rowl[row] * scale + sum;
                rowm[row] = newm;
                rowsc[row] = scale;
            }
        }
        __syncthreads();

        // O = O*scale + P @ V (bf16x3); P hi at row*76 words, lo at +38
        float sc0 = rowsc[m0r], sc1 = rowsc[m1r];
#pragma unroll
        for (int nt = 0; nt < 4; nt++) {
            ofr[nt].x *= sc0; ofr[nt].y *= sc0;
            ofr[nt].z *= sc1; ofr[nt].w *= sc1;
        }
#pragma unroll
        for (int kk = 0; kk < 4; kk++) {
            int a0 = m0r * PSP + kk * 8 + t;
            int a1 = m1r * PSP + kk * 8 + t;
            uint32_t ah0 = PsU[a0],      ah1 = PsU[a1],      ah2 = PsU[a0 + 4],      ah3 = PsU[a1 + 4];
            uint32_t al0 = PsU[a0 + 38], al1 = PsU[a1 + 38], al2 = PsU[a0 + 42],     al3 = PsU[a1 + 42];
#pragma unroll
            for (int nt = 0; nt < 4; nt++) {
                int d  = wn * 32 + nt * 8 + g;
                int bo = d * VP35 + kk * 8 + t;
                uint32_t bh0 = Vh[bo], bh1 = Vh[bo + 4];
                uint32_t bl0 = Vl[bo], bl1 = Vl[bo + 4];
                mma_bf16(ofr[nt], ah0, ah1, ah2, ah3, bh0, bh1);
                mma_bf16(ofr[nt], ah0, ah1, ah2, ah3, bl0, bl1);
                mma_bf16(ofr[nt], al0, al1, al2, al3, bh0, bh1);
            }
        }
    }

    // Final normalize + write fp32 XO and split planes
    float l0 = rowl[m0r], l1 = rowl[m1r];
    float inv0 = (l0 > 0.f) ? (1.f / l0) : 0.f;
    float inv1 = (l1 > 0.f) ? (1.f / l1) : 0.f;
#pragma unroll
    for (int nt = 0; nt < 4; nt++) {
        int c0 = wn * 32 + nt * 8 + 2 * t;
        float o00 = ofr[nt].x * inv0, o01 = ofr[nt].y * inv0;
        float o10 = ofr[nt].z * inv1, o11 = ofr[nt].w * inv1;
        *(float2*)(Op + (long)(q0 + m0r) * C_ + c0) = make_float2(o00, o01);
        *(float2*)(Op + (long)(q0 + m1r) * C_ + c0) = make_float2(o10, o11);
        uint32_t hw, lw;
        split_pair(o00, o01, hw, lw);
        Oph[(long)(q0 + m0r) * 256 + (c0 >> 1)] = hw;
        Opl[(long)(q0 + m0r) * 256 + (c0 >> 1)] = lw;
        split_pair(o10, o11, hw, lw);
        Oph[(long)(q0 + m1r) * 256 + (c0 >> 1)] = hw;
        Opl[(long)(q0 + m1r) * 256 + (c0 >> 1)] = lw;
    }
}

// ---------------------------------------------------------------------------
// Router + aggregation
// ---------------------------------------------------------------------------
__global__ __launch_bounds__(256) void router_kernel(
    const float* __restrict__ rh, const float* __restrict__ rw2,
    const float* __restrict__ rb2, float* __restrict__ sparse)
{
    int gwarp = (blockIdx.x * blockDim.x + threadIdx.x) >> 5;
    int lane  = threadIdx.x & 31;
    if (gwarp >= M_) return;

    const float* r = rh + (long)gwarp * RH_;
    float acc[E_];
#pragma unroll
    for (int e = 0; e < E_; e++) acc[e] = 0.f;
    for (int hh = lane; hh < RH_; hh += 32) {
        float xv = r[hh];
        const float* w = rw2 + hh * E_;
#pragma unroll
        for (int e = 0; e < E_; e++) acc[e] += xv * w[e];
    }
#pragma unroll
    for (int off = 16; off > 0; off >>= 1)
#pragma unroll
        for (int e = 0; e < E_; e++)
            acc[e] += __shfl_xor_sync(0xffffffffu, acc[e], off);

    if (lane == 0) {
        float lg[E_];
        float mx = -1e30f;
#pragma unroll
        for (int e = 0; e < E_; e++) { lg[e] = acc[e] + rb2[e]; mx = fmaxf(mx, lg[e]); }
        float sum = 0.f;
#pragma unroll
        for (int e = 0; e < E_; e++) { lg[e] = __expf(lg[e] - mx); sum += lg[e]; }
        float inv = 1.f / sum;
#pragma unroll
        for (int e = 0; e < E_; e++) lg[e] *= inv;
        int i1 = 0;
#pragma unroll
        for (int e = 1; e < E_; e++) if (lg[e] > lg[i1]) i1 = e;
        int i2 = (i1 == 0) ? 1 : 0;
#pragma unroll
        for (int e = 0; e < E_; e++) if (e != i1 && lg[e] > lg[i2]) i2 = e;
        float denom = fmaxf(lg[i1] + lg[i2], EPS_);
        float outv[E_];
#pragma unroll
        for (int e = 0; e < E_; e++) outv[e] = 0.f;
        outv[i1] = lg[i1] / denom;
        outv[i2] = lg[i2] / denom;
        float* o = sparse + (long)gwarp * E_;
#pragma unroll
        for (int e = 0; e < E_; e++) o[e] = outv[e];
    }
}

__global__ __launch_bounds__(256) void agg_kernel(
    const float* __restrict__ stacked, const float* __restrict__ sparse,
    float* __restrict__ agg)
{
    int idx = blockIdx.x * blockDim.x + threadIdx.x;
    if (idx >= M_ * (C_ / 4)) return;
    int m  = idx >> 7;
    int c  = (idx & 127) << 2;
    const float* sp = sparse + (long)m * E_;
    float w[E_];
#pragma unroll
    for (int e = 0; e < E_; e++) w[e] = sp[e];
    float4 a = {0.f, 0.f, 0.f, 0.f};
#pragma unroll
    for (int e = 0; e < E_; e++) {
        float4 v = *(const float4*)(stacked + ((long)m * E_ + e) * C_ + c);
        a.x += w[e] * v.x; a.y += w[e] * v.y; a.z += w[e] * v.z; a.w += w[e] * v.w;
    }
    *(float4*)(agg + (long)m * C_ + c) = a;
}

// ---------------------------------------------------------------------------
// Launch
// ---------------------------------------------------------------------------
extern "C" void kernel_launch(void* const* d_in, const int* in_sizes, int n_in,
                              void* d_out, int out_size)
{
    const float* x    = (const float*)d_in[0];
    const int*   mask = (const int*)d_in[1];
    const float* qw   = (const float*)d_in[2];
    const float* qb   = (const float*)d_in[3];
    const float* kw   = (const float*)d_in[4];
    const float* kb   = (const float*)d_in[5];
    const float* vw   = (const float*)d_in[6];
    const float* vb   = (const float*)d_in[7];
    const float* fc1w = (const float*)d_in[8];
    const float* fc1b = (const float*)d_in[9];
    const float* fc2w = (const float*)d_in[10];
    const float* fc2b = (const float*)d_in[11];
    const float* rw1  = (const float*)d_in[12];
    const float* rb1  = (const float*)d_in[13];
    const float* rw2  = (const float*)d_in[14];
    const float* rb2  = (const float*)d_in[15];

    float* out     = (float*)d_out;
    float* agg     = out;
    float* stacked = out + STACK_OFF;
    float* sparse  = out + SPARSE_OFF;

    uint32_t *xh, *xl, *wph, *wpl;
    uint32_t *qph, *qpl, *kph, *kpl, *vph, *vpl, *xoph, *xopl, *hph, *hpl;
    float *gxo, *grh;
    cudaGetSymbolAddress((void**)&xh,   g_Xh);
    cudaGetSymbolAddress((void**)&xl,   g_Xl);
    cudaGetSymbolAddress((void**)&wph,  g_Wph);
    cudaGetSymbolAddress((void**)&wpl,  g_Wpl);
    cudaGetSymbolAddress((void**)&qph,  g_Qph);
    cudaGetSymbolAddress((void**)&qpl,  g_Qpl);
    cudaGetSymbolAddress((void**)&kph,  g_Kph);
    cudaGetSymbolAddress((void**)&kpl,  g_Kpl);
    cudaGetSymbolAddress((void**)&vph,  g_Vph);
    cudaGetSymbolAddress((void**)&vpl,  g_Vpl);
    cudaGetSymbolAddress((void**)&xoph, g_XOph);
    cudaGetSymbolAddress((void**)&xopl, g_XOpl);
    cudaGetSymbolAddress((void**)&hph,  g_Hph);
    cudaGetSymbolAddress((void**)&hpl,  g_Hpl);
    cudaGetSymbolAddress((void**)&gxo,  g_XO);
    cudaGetSymbolAddress((void**)&grh,  g_RH);

    cudaFuncSetAttribute(qkv_packed_kernel, cudaFuncAttributeMaxDynamicSharedMemorySize, GSMEM);
    cudaFuncSetAttribute(fc1_packed_kernel, cudaFuncAttributeMaxDynamicSharedMemorySize, GSMEM);
    cudaFuncSetAttribute(fc2_packed_kernel, cudaFuncAttributeMaxDynamicSharedMemorySize, GSMEM);
    cudaFuncSetAttribute(gemm_tf32x3_kernel, cudaFuncAttributeMaxDynamicSharedMemorySize, RSMEM);
    cudaFuncSetAttribute(attn_mma_kernel,    cudaFuncAttributeMaxDynamicSharedMemorySize, ATT_SMEM);

    // Prep: split x and weights into packed bf16 planes
    split_x_kernel<<<XPW / 256, 256>>>(x, xh, xl);
    split_w_kernel<<<WPW / 256, 256>>>(qw, kw, vw, fc1w, fc2w, wph, wpl);

    // Fused QKV (z = set*6 + e)
    {
        dim3 gq(4, 32, 18);
        qkv_packed_kernel<<<gq, 256, GSMEM>>>(xh, xl, wph, wpl, qb, kb, vb,
                                              qph, qpl, kph, kpl, vph, vpl);
    }

    // Attention
    {
        dim3 ag(S_ / 64, H_, E_ * B_);
        attn_mma_kernel<<<ag, 256, ATT_SMEM>>>(qph, qpl, kph, kpl, vph, vpl,
                                               mask, gxo, xoph, xopl);
    }

    // FFN
    {
        dim3 gf(4, 32, 6);
        fc1_packed_kernel<<<gf, 256, GSMEM>>>(xoph, xopl, wph, wpl, fc1b, hph, hpl);
        fc2_packed_kernel<<<gf, 256, GSMEM>>>(hph, hpl, wph, wpl, fc2b, gxo, stacked);
    }

    // Router: tf32x3 rh, then top-2
    {
        dim3 gr(4, 32, 1);
        gemm_tf32x3_kernel<<<gr, 256, RSMEM>>>(x, rw1, rb1, grh);
        router_kernel<<<(M_ * 32 + 255) / 256, 256>>>(grh, rw2, rb2, sparse);
    }

    agg_kernel<<<(M_ * (C_ / 4) + 255) / 256, 256>>>(stacked, sparse, agg);
}